// round 14
// baseline (speedup 1.0000x reference)
#include <cuda_runtime.h>
#include <cuda_fp16.h>

#define NMAX 100000
#define EMAX 1600000
#define ETMAX (EMAX + NMAX)
#define SCAN_CHUNK 1024
#define SCAN_BLOCKS ((NMAX + SCAN_CHUNK - 1) / SCAN_CHUNK)

// ---------------- scratch (static device globals; no allocation) ----------------
__device__ __align__(16) __half g_h1h[NMAX * 128];  // layer1 h fp16; reused for layer2 h fp16 (stride 64)
__device__ __align__(16) __half g_acch[NMAX * 128]; // layer1 output (post BN/ReLU), fp16
__device__ __align__(16) float g_as1[NMAX * 4];
__device__ __align__(16) float g_ad1[NMAX * 4];
__device__ __align__(16) float g_as2[NMAX];
__device__ __align__(16) float g_ad2[NMAX];
__device__ float g_gmax[8];    // [0..3]=max as1 per head, [4..7]=max ad1 per head
__device__ float g_gmax2[2];   // [0]=max as2, [1]=max ad2
__device__ int g_cnt[NMAX];    // INVARIANT: zero on entry (re-zeroed by scan_down)
__device__ int g_rank[EMAX];   // per-edge rank within its dst (from hist)
__device__ int g_row[NMAX + 1];
__device__ int g_csrc[ETMAX];
__device__ int g_part[SCAN_BLOCKS + 1];

#define NEG_SLOPE 0.2f
#define EPS_BN 1e-5f

__device__ __forceinline__ float lrelu(float v) {
    return v > 0.f ? v : NEG_SLOPE * v;
}

__device__ __forceinline__ void atomicMaxF(float* addr, float v) {
    if (v >= 0.f) atomicMax((int*)addr, __float_as_int(v));
    else          atomicMin((unsigned int*)addr, __float_as_uint(v));
}

__device__ __forceinline__ float f2tf32(float f) {
    unsigned u;
    asm("cvt.rna.tf32.f32 %0, %1;" : "=r"(u) : "f"(f));
    return __uint_as_float(u);
}

__device__ __forceinline__ void mma_tf32(float* c, const unsigned* a, const unsigned* b) {
    asm volatile(
        "mma.sync.aligned.m16n8k8.row.col.f32.tf32.tf32.f32 "
        "{%0,%1,%2,%3}, {%4,%5,%6,%7}, {%8,%9}, {%0,%1,%2,%3};\n"
        : "+f"(c[0]), "+f"(c[1]), "+f"(c[2]), "+f"(c[3])
        : "r"(a[0]), "r"(a[1]), "r"(a[2]), "r"(a[3]), "r"(b[0]), "r"(b[1]));
}

// ---------------- [side 1] histogram over dst + per-edge rank + gmax init ----------------
__global__ void hist_kernel(const int* __restrict__ ei, int E) {
    if (blockIdx.x == 0 && threadIdx.x < 10) {
        float ninf = __int_as_float(0xff800000);
        if (threadIdx.x < 8) g_gmax[threadIdx.x] = ninf;
        else                 g_gmax2[threadIdx.x - 8] = ninf;
    }
    int e = blockIdx.x * blockDim.x + threadIdx.x;
    if (e >= E) return;
    int dst = __ldg(&ei[E + e]);
    g_rank[e] = atomicAdd(&g_cnt[dst], 1);
}

// ---------------- [side 2] per-block partial sums (+1 self-loop per node) ----------------
__global__ void scan_part_kernel(int n) {
    __shared__ int sh[256];
    int blk = blockIdx.x;
    int t = threadIdx.x;
    int base = blk * SCAN_CHUNK + t * 4;
    int s = 0;
#pragma unroll
    for (int i = 0; i < 4; i++) {
        int idx = base + i;
        if (idx < n) s += g_cnt[idx] + 1;   // +1 = self-loop
    }
    sh[t] = s;
    __syncthreads();
#pragma unroll
    for (int off = 128; off > 0; off >>= 1) {
        if (t < off) sh[t] += sh[t + off];
        __syncthreads();
    }
    if (t == 0) g_part[blk] = sh[0];
}

// ---------------- [side 3] down-sweep: top scan + local scan + self-loop write + re-zero ----------------
__global__ void scan_down_kernel(int n, int nb) {
    __shared__ int sp[128];
    __shared__ int sh[256];
    int blk = blockIdx.x;
    int t = threadIdx.x;

    if (t < 128) sp[t] = (t < nb) ? g_part[t] : 0;
    __syncthreads();
    for (int off = 1; off < 128; off <<= 1) {
        int u = 0;
        if (t < 128 && t >= off) u = sp[t - off];
        __syncthreads();
        if (t < 128) sp[t] += u;
        __syncthreads();
    }
    if (blk == 0 && t == 0) g_row[n] = sp[nb - 1];
    int blockoff = sp[blk] - g_part[blk];

    int base = blk * SCAN_CHUNK + t * 4;
    int v[4];
    int s = 0;
#pragma unroll
    for (int i = 0; i < 4; i++) {
        int idx = base + i;
        v[i] = (idx < n) ? (g_cnt[idx] + 1) : 0;
        s += v[i];
    }
    sh[t] = s;
    __syncthreads();
    for (int off = 1; off < 256; off <<= 1) {
        int u = (t >= off) ? sh[t - off] : 0;
        __syncthreads();
        sh[t] += u;
        __syncthreads();
    }
    int running = sh[t] - s + blockoff;
#pragma unroll
    for (int i = 0; i < 4; i++) {
        int idx = base + i;
        if (idx < n) {
            g_row[idx] = running;
            g_csrc[running] = idx;   // self-loop src at row start
            g_cnt[idx] = 0;          // restore invariant for next replay
            running += v[i];
        }
    }
}

// ---------------- [side 4] deterministic scatter via per-edge rank (no atomics) ----------------
__global__ void scatter_kernel(const int* __restrict__ ei, int E) {
    int e = blockIdx.x * blockDim.x + threadIdx.x;
    if (e >= E) return;
    int src = __ldg(&ei[e]);
    int dst = __ldg(&ei[E + e]);
    int rank = g_rank[e];
    g_csrc[__ldg(&g_row[dst]) + 1 + rank] = src;
}

// ---------------- [main 1] layer 1 GEMM (tensor core, tf32) + fused scores + gmax ----------------
__global__ void __launch_bounds__(256) gemm1_tc_kernel(
    const float* __restrict__ A, const float* __restrict__ W,
    const float* __restrict__ att_s, const float* __restrict__ att_d, int n) {
    __shared__ float sA[128][36];
    __shared__ float sW[32][136];

    int tid = threadIdx.x;
    int warp = tid >> 5, lane = tid & 31;
    int gid = lane >> 2, tig = lane & 3;
    int mwarp = warp >> 2, nwarp = warp & 3;
    int row0 = blockIdx.x * 128;

    float acc[4][4][4];
#pragma unroll
    for (int mt = 0; mt < 4; mt++)
#pragma unroll
        for (int nt = 0; nt < 4; nt++)
#pragma unroll
            for (int r = 0; r < 4; r++) acc[mt][nt][r] = 0.f;

    for (int kc = 0; kc < 4; kc++) {
        int k0 = kc * 32;
        __syncthreads();
#pragma unroll
        for (int rep = 0; rep < 4; rep++) {
            int f = tid + rep * 256;
            int r = f >> 3, c4 = f & 7;
            int gr = row0 + r;
            float4 v = make_float4(0.f, 0.f, 0.f, 0.f);
            if (gr < n) v = *(const float4*)&A[gr * 128 + k0 + c4 * 4];
            float4 t = make_float4(f2tf32(v.x), f2tf32(v.y), f2tf32(v.z), f2tf32(v.w));
            *(float4*)&sA[r][c4 * 4] = t;
        }
#pragma unroll
        for (int rep = 0; rep < 4; rep++) {
            int f = tid + rep * 256;
            int kr = f >> 5, c4 = f & 31;
            float4 v = *(const float4*)&W[(k0 + kr) * 128 + c4 * 4];
            float4 t = make_float4(f2tf32(v.x), f2tf32(v.y), f2tf32(v.z), f2tf32(v.w));
            *(float4*)&sW[kr][c4 * 4] = t;
        }
        __syncthreads();
#pragma unroll
        for (int ks = 0; ks < 4; ks++) {
            int kk = ks * 8;
            unsigned b[4][2], a[4][4];
#pragma unroll
            for (int nt = 0; nt < 4; nt++) {
                int c = nwarp * 32 + nt * 8 + gid;
                b[nt][0] = __float_as_uint(sW[kk + tig][c]);
                b[nt][1] = __float_as_uint(sW[kk + tig + 4][c]);
            }
#pragma unroll
            for (int mt = 0; mt < 4; mt++) {
                int r = mwarp * 64 + mt * 16 + gid;
                a[mt][0] = __float_as_uint(sA[r][kk + tig]);
                a[mt][1] = __float_as_uint(sA[r + 8][kk + tig]);
                a[mt][2] = __float_as_uint(sA[r][kk + tig + 4]);
                a[mt][3] = __float_as_uint(sA[r + 8][kk + tig + 4]);
            }
#pragma unroll
            for (int mt = 0; mt < 4; mt++)
#pragma unroll
                for (int nt = 0; nt < 4; nt++) mma_tf32(acc[mt][nt], a[mt], b[nt]);
        }
    }

    float asr[8], adr[8];
#pragma unroll
    for (int nt = 0; nt < 4; nt++) {
        int c = nwarp * 32 + nt * 8 + tig * 2;
        asr[nt * 2 + 0] = att_s[c];
        asr[nt * 2 + 1] = att_s[c + 1];
        adr[nt * 2 + 0] = att_d[c];
        adr[nt * 2 + 1] = att_d[c + 1];
    }
    float mxs = __int_as_float(0xff800000), mxd = __int_as_float(0xff800000);
#pragma unroll
    for (int mt = 0; mt < 4; mt++) {
#pragma unroll
        for (int half = 0; half < 2; half++) {
            int r = row0 + mwarp * 64 + mt * 16 + gid + half * 8;
            float sa = 0.f, sd = 0.f;
            if (r < n) {
#pragma unroll
                for (int nt = 0; nt < 4; nt++) {
                    float c0 = acc[mt][nt][half * 2 + 0];
                    float c1 = acc[mt][nt][half * 2 + 1];
                    int col = nwarp * 32 + nt * 8 + tig * 2;
                    *(__half2*)&g_h1h[r * 128 + col] =
                        __float22half2_rn(make_float2(c0, c1));
                    sa += c0 * asr[nt * 2] + c1 * asr[nt * 2 + 1];
                    sd += c0 * adr[nt * 2] + c1 * adr[nt * 2 + 1];
                }
            }
            sa += __shfl_xor_sync(0xffffffffu, sa, 1);
            sa += __shfl_xor_sync(0xffffffffu, sa, 2);
            sd += __shfl_xor_sync(0xffffffffu, sd, 1);
            sd += __shfl_xor_sync(0xffffffffu, sd, 2);
            if (r < n) {
                mxs = fmaxf(mxs, sa);
                mxd = fmaxf(mxd, sd);
                if (tig == 0) {
                    g_as1[r * 4 + nwarp] = sa;
                    g_ad1[r * 4 + nwarp] = sd;
                }
            }
        }
    }
#pragma unroll
    for (int off = 16; off > 0; off >>= 1) {
        mxs = fmaxf(mxs, __shfl_xor_sync(0xffffffffu, mxs, off));
        mxd = fmaxf(mxd, __shfl_xor_sync(0xffffffffu, mxd, off));
    }
    if (lane == 0) {
        atomicMaxF(&g_gmax[nwarp], mxs);
        atomicMaxF(&g_gmax[4 + nwarp], mxd);
    }
}

// ---------------- [main 2] layer 1 gather: 2 warps/node, contiguous halves, smem combine ----------------
__global__ void gat1_gather_kernel(const float* __restrict__ b1,
                                   const float* __restrict__ gamma,
                                   const float* __restrict__ beta,
                                   const float* __restrict__ mean,
                                   const float* __restrict__ var,
                                   int wbase, int wend) {
    __shared__ float sAcc[4][132];
    __shared__ float sSum[4][32];

    int gw = (blockIdx.x * blockDim.x + threadIdx.x) >> 5;  // global warp
    int w = wbase + (gw >> 1);
    int half = gw & 1;
    int wid = threadIdx.x >> 5;
    int pair = wid >> 1;
    int lane = threadIdx.x & 31;
    bool active = (w < wend);
    int h = lane >> 3;
    int cb = lane * 4;

    float4 acc = make_float4(0.f, 0.f, 0.f, 0.f);
    float ssum = 0.f;
    float ad = 0.f, ub = 0.f;

    if (active) {
        int beg0 = g_row[w], end0 = g_row[w + 1];
        int mid = (beg0 + end0 + 1) >> 1;
        int beg = half ? mid : beg0;
        int end = half ? end0 : mid;
        ad = g_ad1[w * 4 + h];
        ub = lrelu(g_gmax[h] + g_gmax[4 + h]);

        int e = beg;
        for (; e + 8 <= end; e += 8) {
            int sv[8];
#pragma unroll
            for (int j = 0; j < 8; j++) sv[j] = __ldg(&g_csrc[e + j]);
            float av[8];
#pragma unroll
            for (int j = 0; j < 8; j++) av[j] = __ldg(&g_as1[sv[j] * 4 + h]);
            uint2 hv[8];
#pragma unroll
            for (int j = 0; j < 8; j++) hv[j] = __ldg((const uint2*)&g_h1h[sv[j] * 128 + cb]);
#pragma unroll
            for (int j = 0; j < 8; j++) {
                float p = __expf(lrelu(av[j] + ad) - ub);
                ssum += p;
                float2 f01 = __half22float2(*(__half2*)&hv[j].x);
                float2 f23 = __half22float2(*(__half2*)&hv[j].y);
                acc.x += p * f01.x;
                acc.y += p * f01.y;
                acc.z += p * f23.x;
                acc.w += p * f23.y;
            }
        }
        for (; e + 4 <= end; e += 4) {
            int sv[4];
#pragma unroll
            for (int j = 0; j < 4; j++) sv[j] = __ldg(&g_csrc[e + j]);
            float av[4];
#pragma unroll
            for (int j = 0; j < 4; j++) av[j] = __ldg(&g_as1[sv[j] * 4 + h]);
            uint2 hv[4];
#pragma unroll
            for (int j = 0; j < 4; j++) hv[j] = __ldg((const uint2*)&g_h1h[sv[j] * 128 + cb]);
#pragma unroll
            for (int j = 0; j < 4; j++) {
                float p = __expf(lrelu(av[j] + ad) - ub);
                ssum += p;
                float2 f01 = __half22float2(*(__half2*)&hv[j].x);
                float2 f23 = __half22float2(*(__half2*)&hv[j].y);
                acc.x += p * f01.x;
                acc.y += p * f01.y;
                acc.z += p * f23.x;
                acc.w += p * f23.y;
            }
        }
        for (; e < end; e++) {
            int s0 = __ldg(&g_csrc[e]);
            float a0 = __ldg(&g_as1[s0 * 4 + h]);
            uint2 v0 = __ldg((const uint2*)&g_h1h[s0 * 128 + cb]);
            float p0 = __expf(lrelu(a0 + ad) - ub);
            ssum += p0;
            float2 f01 = __half22float2(*(__half2*)&v0.x);
            float2 f23 = __half22float2(*(__half2*)&v0.y);
            acc.x += p0 * f01.x;
            acc.y += p0 * f01.y;
            acc.z += p0 * f23.x;
            acc.w += p0 * f23.y;
        }
    }

    // combine: odd warp deposits, even warp finishes
    if (half == 1 && active) {
        sAcc[pair][cb + 0] = acc.x;
        sAcc[pair][cb + 1] = acc.y;
        sAcc[pair][cb + 2] = acc.z;
        sAcc[pair][cb + 3] = acc.w;
        sSum[pair][lane] = ssum;
    }
    __syncthreads();
    if (half == 0 && active) {
        acc.x += sAcc[pair][cb + 0];
        acc.y += sAcc[pair][cb + 1];
        acc.z += sAcc[pair][cb + 2];
        acc.w += sAcc[pair][cb + 3];
        ssum += sSum[pair][lane];

        float inv = 1.f / ssum;
        float o[4];
#pragma unroll
        for (int j = 0; j < 4; j++) {
            float v = ((&acc.x)[j]) * inv + b1[cb + j];
            v = gamma[cb + j] * (v - mean[cb + j]) * rsqrtf(var[cb + j] + EPS_BN) + beta[cb + j];
            o[j] = fmaxf(v, 0.f);
        }
        __half2 p0 = __float22half2_rn(make_float2(o[0], o[1]));
        __half2 p1 = __float22half2_rn(make_float2(o[2], o[3]));
        uint2 pk;
        pk.x = *(unsigned*)&p0;
        pk.y = *(unsigned*)&p1;
        *(uint2*)&g_acch[w * 128 + cb] = pk;
    }
}

// ---------------- [main 3] layer 2 GEMM (tc tf32, fp16 A in): h2 -> fp16, scores, gmax ----------------
__global__ void __launch_bounds__(256) gemm2_tc_kernel(
    const float* __restrict__ W,
    const float* __restrict__ att_s, const float* __restrict__ att_d,
    int rowbase, int n) {
    __shared__ float sA[128][36];
    __shared__ float sW[32][72];

    int tid = threadIdx.x;
    int warp = tid >> 5, lane = tid & 31;
    int gid = lane >> 2, tig = lane & 3;
    int row0 = rowbase + blockIdx.x * 128;

    float acc[8][4];
#pragma unroll
    for (int nt = 0; nt < 8; nt++)
#pragma unroll
        for (int r = 0; r < 4; r++) acc[nt][r] = 0.f;

    for (int kc = 0; kc < 4; kc++) {
        int k0 = kc * 32;
        __syncthreads();
#pragma unroll
        for (int rep = 0; rep < 4; rep++) {
            int f = tid + rep * 256;
            int r = f >> 3, c4 = f & 7;
            int gr = row0 + r;
            float4 t = make_float4(0.f, 0.f, 0.f, 0.f);
            if (gr < n) {
                uint2 hv = *(const uint2*)&g_acch[gr * 128 + k0 + c4 * 4];
                float2 f01 = __half22float2(*(__half2*)&hv.x);
                float2 f23 = __half22float2(*(__half2*)&hv.y);
                t = make_float4(f2tf32(f01.x), f2tf32(f01.y), f2tf32(f23.x), f2tf32(f23.y));
            }
            *(float4*)&sA[r][c4 * 4] = t;
        }
#pragma unroll
        for (int rep = 0; rep < 2; rep++) {
            int f = tid + rep * 256;
            int kr = f >> 4, c4 = f & 15;
            float4 v = *(const float4*)&W[(k0 + kr) * 64 + c4 * 4];
            float4 t = make_float4(f2tf32(v.x), f2tf32(v.y), f2tf32(v.z), f2tf32(v.w));
            *(float4*)&sW[kr][c4 * 4] = t;
        }
        __syncthreads();
#pragma unroll
        for (int ks = 0; ks < 4; ks++) {
            int kk = ks * 8;
            unsigned a[4], b[8][2];
            {
                int r = warp * 16 + gid;
                a[0] = __float_as_uint(sA[r][kk + tig]);
                a[1] = __float_as_uint(sA[r + 8][kk + tig]);
                a[2] = __float_as_uint(sA[r][kk + tig + 4]);
                a[3] = __float_as_uint(sA[r + 8][kk + tig + 4]);
            }
#pragma unroll
            for (int nt = 0; nt < 8; nt++) {
                int c = nt * 8 + gid;
                b[nt][0] = __float_as_uint(sW[kk + tig][c]);
                b[nt][1] = __float_as_uint(sW[kk + tig + 4][c]);
            }
#pragma unroll
            for (int nt = 0; nt < 8; nt++) mma_tf32(acc[nt], a, b[nt]);
        }
    }

    float asr[16], adr[16];
#pragma unroll
    for (int nt = 0; nt < 8; nt++) {
        int c = nt * 8 + tig * 2;
        asr[nt * 2 + 0] = att_s[c];
        asr[nt * 2 + 1] = att_s[c + 1];
        adr[nt * 2 + 0] = att_d[c];
        adr[nt * 2 + 1] = att_d[c + 1];
    }
    float mxs = __int_as_float(0xff800000), mxd = __int_as_float(0xff800000);
#pragma unroll
    for (int half = 0; half < 2; half++) {
        int r = row0 + warp * 16 + gid + half * 8;
        float sa = 0.f, sd = 0.f;
        if (r < n) {
#pragma unroll
            for (int nt = 0; nt < 8; nt++) {
                float c0 = acc[nt][half * 2 + 0];
                float c1 = acc[nt][half * 2 + 1];
                int col = nt * 8 + tig * 2;
                *(__half2*)&g_h1h[r * 64 + col] =
                    __float22half2_rn(make_float2(c0, c1));
                sa += c0 * asr[nt * 2] + c1 * asr[nt * 2 + 1];
                sd += c0 * adr[nt * 2] + c1 * adr[nt * 2 + 1];
            }
        }
        sa += __shfl_xor_sync(0xffffffffu, sa, 1);
        sa += __shfl_xor_sync(0xffffffffu, sa, 2);
        sd += __shfl_xor_sync(0xffffffffu, sd, 1);
        sd += __shfl_xor_sync(0xffffffffu, sd, 2);
        if (r < n) {
            mxs = fmaxf(mxs, sa);
            mxd = fmaxf(mxd, sd);
            if (tig == 0) {
                g_as2[r] = sa;
                g_ad2[r] = sd;
            }
        }
    }
#pragma unroll
    for (int off = 16; off > 0; off >>= 1) {
        mxs = fmaxf(mxs, __shfl_xor_sync(0xffffffffu, mxs, off));
        mxd = fmaxf(mxd, __shfl_xor_sync(0xffffffffu, mxd, off));
    }
    if (lane == 0) {
        atomicMaxF(&g_gmax2[0], mxs);
        atomicMaxF(&g_gmax2[1], mxd);
    }
}

// ---------------- [main 4] layer 2 gather: 2 warps/node, smem combine ----------------
__global__ void gat2_gather_kernel(float* __restrict__ out,
                                   const float* __restrict__ b2,
                                   const float* __restrict__ gamma,
                                   const float* __restrict__ beta,
                                   const float* __restrict__ mean,
                                   const float* __restrict__ var, int n) {
    __shared__ float sAcc[4][68];
    __shared__ float sSum[4][32];

    int gw = (blockIdx.x * blockDim.x + threadIdx.x) >> 5;
    int w = gw >> 1;
    int half = gw & 1;
    int wid = threadIdx.x >> 5;
    int pair = wid >> 1;
    int lane = threadIdx.x & 31;
    bool active = (w < n);
    int cb = lane * 2;

    float2 acc = make_float2(0.f, 0.f);
    float ssum = 0.f;

    if (active) {
        int beg0 = g_row[w], end0 = g_row[w + 1];
        int mid = (beg0 + end0 + 1) >> 1;
        int beg = half ? mid : beg0;
        int end = half ? end0 : mid;
        float ad = g_ad2[w];
        float ub = lrelu(g_gmax2[0] + g_gmax2[1]);

        int e = beg;
        for (; e + 8 <= end; e += 8) {
            int sv[8];
#pragma unroll
            for (int j = 0; j < 8; j++) sv[j] = __ldg(&g_csrc[e + j]);
            float av[8];
#pragma unroll
            for (int j = 0; j < 8; j++) av[j] = __ldg(&g_as2[sv[j]]);
            unsigned hv[8];
#pragma unroll
            for (int j = 0; j < 8; j++) hv[j] = __ldg((const unsigned*)&g_h1h[sv[j] * 64 + cb]);
#pragma unroll
            for (int j = 0; j < 8; j++) {
                float p = __expf(lrelu(av[j] + ad) - ub);
                ssum += p;
                float2 f = __half22float2(*(__half2*)&hv[j]);
                acc.x += p * f.x;
                acc.y += p * f.y;
            }
        }
        for (; e + 4 <= end; e += 4) {
            int sv[4];
#pragma unroll
            for (int j = 0; j < 4; j++) sv[j] = __ldg(&g_csrc[e + j]);
            float av[4];
#pragma unroll
            for (int j = 0; j < 4; j++) av[j] = __ldg(&g_as2[sv[j]]);
            unsigned hv[4];
#pragma unroll
            for (int j = 0; j < 4; j++) hv[j] = __ldg((const unsigned*)&g_h1h[sv[j] * 64 + cb]);
#pragma unroll
            for (int j = 0; j < 4; j++) {
                float p = __expf(lrelu(av[j] + ad) - ub);
                ssum += p;
                float2 f = __half22float2(*(__half2*)&hv[j]);
                acc.x += p * f.x;
                acc.y += p * f.y;
            }
        }
        for (; e < end; e++) {
            int s0 = __ldg(&g_csrc[e]);
            float a0 = __ldg(&g_as2[s0]);
            unsigned v0 = __ldg((const unsigned*)&g_h1h[s0 * 64 + cb]);
            float p0 = __expf(lrelu(a0 + ad) - ub);
            ssum += p0;
            float2 f = __half22float2(*(__half2*)&v0);
            acc.x += p0 * f.x;
            acc.y += p0 * f.y;
        }
    }

    if (half == 1 && active) {
        sAcc[pair][cb + 0] = acc.x;
        sAcc[pair][cb + 1] = acc.y;
        sSum[pair][lane] = ssum;
    }
    __syncthreads();
    if (half == 0 && active) {
        acc.x += sAcc[pair][cb + 0];
        acc.y += sAcc[pair][cb + 1];
        ssum += sSum[pair][lane];

        float inv = 1.f / ssum;
        float vx = acc.x * inv + b2[cb];
        float vy = acc.y * inv + b2[cb + 1];
        vx = gamma[cb] * (vx - mean[cb]) * rsqrtf(var[cb] + EPS_BN) + beta[cb];
        vy = gamma[cb + 1] * (vy - mean[cb + 1]) * rsqrtf(var[cb + 1] + EPS_BN) + beta[cb + 1];
        *(float2*)&out[w * 64 + cb] = make_float2(vx, vy);
    }
}

// ---------------- launcher: fork CSR || gemm1; pipeline gat1 || gemm2 halves ----------------
extern "C" void kernel_launch(void* const* d_in, const int* in_sizes, int n_in,
                              void* d_out, int out_size) {
    const float* x        = (const float*)d_in[0];
    const int*   ei       = (const int*)d_in[1];   // int32 (JAX demotes int64)
    const float* W1       = (const float*)d_in[2];
    const float* att_src1 = (const float*)d_in[3];
    const float* att_dst1 = (const float*)d_in[4];
    const float* b1       = (const float*)d_in[5];
    const float* bn1_g    = (const float*)d_in[6];
    const float* bn1_b    = (const float*)d_in[7];
    const float* bn1_m    = (const float*)d_in[8];
    const float* bn1_v    = (const float*)d_in[9];
    const float* W2       = (const float*)d_in[10];
    const float* att_src2 = (const float*)d_in[11];
    const float* att_dst2 = (const float*)d_in[12];
    const float* b2       = (const float*)d_in[13];
    const float* bn2_g    = (const float*)d_in[14];
    const float* bn2_b    = (const float*)d_in[15];
    const float* bn2_m    = (const float*)d_in[16];
    const float* bn2_v    = (const float*)d_in[17];
    float* out = (float*)d_out;

    int n = in_sizes[0] / 128;
    int E = in_sizes[1] / 2;
    int nb = (n + SCAN_CHUNK - 1) / SCAN_CHUNK;

    const int B = 256;

    static cudaStream_t side = nullptr;
    static cudaEvent_t evFork = nullptr, evJoin = nullptr, evG1a = nullptr, evG2a = nullptr;
    if (side == nullptr) {
        cudaStreamCreateWithFlags(&side, cudaStreamNonBlocking);
        cudaEventCreateWithFlags(&evFork, cudaEventDisableTiming);
        cudaEventCreateWithFlags(&evJoin, cudaEventDisableTiming);
        cudaEventCreateWithFlags(&evG1a, cudaEventDisableTiming);
        cudaEventCreateWithFlags(&evG2a, cudaEventDisableTiming);
    }

    // ---- fork: CSR build on side stream, gemm1 on main stream ----
    cudaEventRecord(evFork, 0);
    cudaStreamWaitEvent(side, evFork, 0);

    hist_kernel<<<(E + B - 1) / B, B, 0, side>>>(ei, E);
    scan_part_kernel<<<nb, 256, 0, side>>>(n);
    scan_down_kernel<<<nb, 256, 0, side>>>(n, nb);
    scatter_kernel<<<(E + B - 1) / B, B, 0, side>>>(ei, E);
    cudaEventRecord(evJoin, side);

    gemm1_tc_kernel<<<(n + 127) / 128, 256>>>(x, W1, att_src1, att_dst1, n);

    // ---- join CSR, then pipelined gat1 || gemm2 ----
    cudaStreamWaitEvent(0, evJoin, 0);

    int half = ((n / 2 + 127) / 128) * 128;  // row-split aligned to gemm2 tiles
    if (half > n) half = n;
    int cnt1 = half, cnt2 = n - half;

    // gat1 first half (main): 2 warps per node -> 64 threads per node
    gat1_gather_kernel<<<(cnt1 * 64 + B - 1) / B, B>>>(b1, bn1_g, bn1_b, bn1_m, bn1_v, 0, half);
    cudaEventRecord(evG1a, 0);

    // gemm2 first half (side, overlaps gat1 second half)
    cudaStreamWaitEvent(side, evG1a, 0);
    gemm2_tc_kernel<<<(cnt1 + 127) / 128, 256, 0, side>>>(W2, att_src2, att_dst2, 0, n);
    cudaEventRecord(evG2a, side);

    // gat1 second half + gemm2 second half (main)
    if (cnt2 > 0) {
        gat1_gather_kernel<<<(cnt2 * 64 + B - 1) / B, B>>>(b1, bn1_g, bn1_b, bn1_m, bn1_v, half, n);
        gemm2_tc_kernel<<<(cnt2 + 127) / 128, 256>>>(W2, att_src2, att_dst2, half, n);
    }

    // join gemm2a, then final gather (2 warps per node)
    cudaStreamWaitEvent(0, evG2a, 0);
    gat2_gather_kernel<<<(n * 64 + B - 1) / B, B>>>(out, b2, bn2_g, bn2_b, bn2_m, bn2_v, n);
}

// round 15
// speedup vs baseline: 1.1710x; 1.1710x over previous
#include <cuda_runtime.h>
#include <cuda_fp16.h>

#define NMAX 100000
#define EMAX 1600000
#define ETMAX (EMAX + NMAX)
#define SCAN_CHUNK 1024
#define SCAN_BLOCKS ((NMAX + SCAN_CHUNK - 1) / SCAN_CHUNK)

// ---------------- scratch (static device globals; no allocation) ----------------
__device__ __align__(16) __half g_h1h[NMAX * 128];  // layer1 h fp16; reused for layer2 h fp16 (stride 64)
__device__ __align__(16) __half g_acch[NMAX * 128]; // layer1 output (post BN/ReLU), fp16
__device__ __align__(16) float g_as1[NMAX * 4];
__device__ __align__(16) float g_ad1[NMAX * 4];
__device__ __align__(16) float g_as2[NMAX];
__device__ __align__(16) float g_ad2[NMAX];
__device__ float g_gmax[8];    // [0..3]=max as1 per head, [4..7]=max ad1 per head
__device__ float g_gmax2[2];   // [0]=max as2, [1]=max ad2
__device__ int g_cnt[NMAX];    // INVARIANT: zero on entry (re-zeroed by scan_down)
__device__ int g_rank[EMAX];   // per-edge rank within its dst (from hist)
__device__ int g_row[NMAX + 1];
__device__ int g_csrc[ETMAX];
__device__ int g_part[SCAN_BLOCKS + 1];

#define NEG_SLOPE 0.2f
#define EPS_BN 1e-5f

__device__ __forceinline__ float lrelu(float v) {
    return v > 0.f ? v : NEG_SLOPE * v;
}

__device__ __forceinline__ void atomicMaxF(float* addr, float v) {
    if (v >= 0.f) atomicMax((int*)addr, __float_as_int(v));
    else          atomicMin((unsigned int*)addr, __float_as_uint(v));
}

__device__ __forceinline__ float f2tf32(float f) {
    unsigned u;
    asm("cvt.rna.tf32.f32 %0, %1;" : "=r"(u) : "f"(f));
    return __uint_as_float(u);
}

__device__ __forceinline__ void mma_tf32(float* c, const unsigned* a, const unsigned* b) {
    asm volatile(
        "mma.sync.aligned.m16n8k8.row.col.f32.tf32.tf32.f32 "
        "{%0,%1,%2,%3}, {%4,%5,%6,%7}, {%8,%9}, {%0,%1,%2,%3};\n"
        : "+f"(c[0]), "+f"(c[1]), "+f"(c[2]), "+f"(c[3])
        : "r"(a[0]), "r"(a[1]), "r"(a[2]), "r"(a[3]), "r"(b[0]), "r"(b[1]));
}

// ---------------- [side 1] histogram over dst + per-edge rank + gmax init ----------------
__global__ void hist_kernel(const int* __restrict__ ei, int E) {
    if (blockIdx.x == 0 && threadIdx.x < 10) {
        float ninf = __int_as_float(0xff800000);
        if (threadIdx.x < 8) g_gmax[threadIdx.x] = ninf;
        else                 g_gmax2[threadIdx.x - 8] = ninf;
    }
    int e = blockIdx.x * blockDim.x + threadIdx.x;
    if (e >= E) return;
    int dst = __ldg(&ei[E + e]);
    g_rank[e] = atomicAdd(&g_cnt[dst], 1);
}

// ---------------- [side 2] per-block partial sums (+1 self-loop per node) ----------------
__global__ void scan_part_kernel(int n) {
    __shared__ int sh[256];
    int blk = blockIdx.x;
    int t = threadIdx.x;
    int base = blk * SCAN_CHUNK + t * 4;
    int s = 0;
#pragma unroll
    for (int i = 0; i < 4; i++) {
        int idx = base + i;
        if (idx < n) s += g_cnt[idx] + 1;   // +1 = self-loop
    }
    sh[t] = s;
    __syncthreads();
#pragma unroll
    for (int off = 128; off > 0; off >>= 1) {
        if (t < off) sh[t] += sh[t + off];
        __syncthreads();
    }
    if (t == 0) g_part[blk] = sh[0];
}

// ---------------- [side 3] down-sweep: top scan + local scan + self-loop write + re-zero ----------------
__global__ void scan_down_kernel(int n, int nb) {
    __shared__ int sp[128];
    __shared__ int sh[256];
    int blk = blockIdx.x;
    int t = threadIdx.x;

    if (t < 128) sp[t] = (t < nb) ? g_part[t] : 0;
    __syncthreads();
    for (int off = 1; off < 128; off <<= 1) {
        int u = 0;
        if (t < 128 && t >= off) u = sp[t - off];
        __syncthreads();
        if (t < 128) sp[t] += u;
        __syncthreads();
    }
    if (blk == 0 && t == 0) g_row[n] = sp[nb - 1];
    int blockoff = sp[blk] - g_part[blk];

    int base = blk * SCAN_CHUNK + t * 4;
    int v[4];
    int s = 0;
#pragma unroll
    for (int i = 0; i < 4; i++) {
        int idx = base + i;
        v[i] = (idx < n) ? (g_cnt[idx] + 1) : 0;
        s += v[i];
    }
    sh[t] = s;
    __syncthreads();
    for (int off = 1; off < 256; off <<= 1) {
        int u = (t >= off) ? sh[t - off] : 0;
        __syncthreads();
        sh[t] += u;
        __syncthreads();
    }
    int running = sh[t] - s + blockoff;
#pragma unroll
    for (int i = 0; i < 4; i++) {
        int idx = base + i;
        if (idx < n) {
            g_row[idx] = running;
            g_csrc[running] = idx;   // self-loop src at row start
            g_cnt[idx] = 0;          // restore invariant for next replay
            running += v[i];
        }
    }
}

// ---------------- [side 4] deterministic scatter via per-edge rank (no atomics) ----------------
__global__ void scatter_kernel(const int* __restrict__ ei, int E) {
    int e = blockIdx.x * blockDim.x + threadIdx.x;
    if (e >= E) return;
    int src = __ldg(&ei[e]);
    int dst = __ldg(&ei[E + e]);
    int rank = g_rank[e];
    g_csrc[__ldg(&g_row[dst]) + 1 + rank] = src;
}

// ---------------- [main 1] layer 1 GEMM (tensor core, tf32) + fused scores + gmax ----------------
__global__ void __launch_bounds__(256) gemm1_tc_kernel(
    const float* __restrict__ A, const float* __restrict__ W,
    const float* __restrict__ att_s, const float* __restrict__ att_d, int n) {
    __shared__ float sA[128][36];
    __shared__ float sW[32][136];

    int tid = threadIdx.x;
    int warp = tid >> 5, lane = tid & 31;
    int gid = lane >> 2, tig = lane & 3;
    int mwarp = warp >> 2, nwarp = warp & 3;
    int row0 = blockIdx.x * 128;

    float acc[4][4][4];
#pragma unroll
    for (int mt = 0; mt < 4; mt++)
#pragma unroll
        for (int nt = 0; nt < 4; nt++)
#pragma unroll
            for (int r = 0; r < 4; r++) acc[mt][nt][r] = 0.f;

    for (int kc = 0; kc < 4; kc++) {
        int k0 = kc * 32;
        __syncthreads();
#pragma unroll
        for (int rep = 0; rep < 4; rep++) {
            int f = tid + rep * 256;
            int r = f >> 3, c4 = f & 7;
            int gr = row0 + r;
            float4 v = make_float4(0.f, 0.f, 0.f, 0.f);
            if (gr < n) v = *(const float4*)&A[gr * 128 + k0 + c4 * 4];
            float4 t = make_float4(f2tf32(v.x), f2tf32(v.y), f2tf32(v.z), f2tf32(v.w));
            *(float4*)&sA[r][c4 * 4] = t;
        }
#pragma unroll
        for (int rep = 0; rep < 4; rep++) {
            int f = tid + rep * 256;
            int kr = f >> 5, c4 = f & 31;
            float4 v = *(const float4*)&W[(k0 + kr) * 128 + c4 * 4];
            float4 t = make_float4(f2tf32(v.x), f2tf32(v.y), f2tf32(v.z), f2tf32(v.w));
            *(float4*)&sW[kr][c4 * 4] = t;
        }
        __syncthreads();
#pragma unroll
        for (int ks = 0; ks < 4; ks++) {
            int kk = ks * 8;
            unsigned b[4][2], a[4][4];
#pragma unroll
            for (int nt = 0; nt < 4; nt++) {
                int c = nwarp * 32 + nt * 8 + gid;
                b[nt][0] = __float_as_uint(sW[kk + tig][c]);
                b[nt][1] = __float_as_uint(sW[kk + tig + 4][c]);
            }
#pragma unroll
            for (int mt = 0; mt < 4; mt++) {
                int r = mwarp * 64 + mt * 16 + gid;
                a[mt][0] = __float_as_uint(sA[r][kk + tig]);
                a[mt][1] = __float_as_uint(sA[r + 8][kk + tig]);
                a[mt][2] = __float_as_uint(sA[r][kk + tig + 4]);
                a[mt][3] = __float_as_uint(sA[r + 8][kk + tig + 4]);
            }
#pragma unroll
            for (int mt = 0; mt < 4; mt++)
#pragma unroll
                for (int nt = 0; nt < 4; nt++) mma_tf32(acc[mt][nt], a[mt], b[nt]);
        }
    }

    float asr[8], adr[8];
#pragma unroll
    for (int nt = 0; nt < 4; nt++) {
        int c = nwarp * 32 + nt * 8 + tig * 2;
        asr[nt * 2 + 0] = att_s[c];
        asr[nt * 2 + 1] = att_s[c + 1];
        adr[nt * 2 + 0] = att_d[c];
        adr[nt * 2 + 1] = att_d[c + 1];
    }
    float mxs = __int_as_float(0xff800000), mxd = __int_as_float(0xff800000);
#pragma unroll
    for (int mt = 0; mt < 4; mt++) {
#pragma unroll
        for (int half = 0; half < 2; half++) {
            int r = row0 + mwarp * 64 + mt * 16 + gid + half * 8;
            float sa = 0.f, sd = 0.f;
            if (r < n) {
#pragma unroll
                for (int nt = 0; nt < 4; nt++) {
                    float c0 = acc[mt][nt][half * 2 + 0];
                    float c1 = acc[mt][nt][half * 2 + 1];
                    int col = nwarp * 32 + nt * 8 + tig * 2;
                    *(__half2*)&g_h1h[r * 128 + col] =
                        __float22half2_rn(make_float2(c0, c1));
                    sa += c0 * asr[nt * 2] + c1 * asr[nt * 2 + 1];
                    sd += c0 * adr[nt * 2] + c1 * adr[nt * 2 + 1];
                }
            }
            sa += __shfl_xor_sync(0xffffffffu, sa, 1);
            sa += __shfl_xor_sync(0xffffffffu, sa, 2);
            sd += __shfl_xor_sync(0xffffffffu, sd, 1);
            sd += __shfl_xor_sync(0xffffffffu, sd, 2);
            if (r < n) {
                mxs = fmaxf(mxs, sa);
                mxd = fmaxf(mxd, sd);
                if (tig == 0) {
                    g_as1[r * 4 + nwarp] = sa;
                    g_ad1[r * 4 + nwarp] = sd;
                }
            }
        }
    }
#pragma unroll
    for (int off = 16; off > 0; off >>= 1) {
        mxs = fmaxf(mxs, __shfl_xor_sync(0xffffffffu, mxs, off));
        mxd = fmaxf(mxd, __shfl_xor_sync(0xffffffffu, mxd, off));
    }
    if (lane == 0) {
        atomicMaxF(&g_gmax[nwarp], mxs);
        atomicMaxF(&g_gmax[4 + nwarp], mxd);
    }
}

// ---------------- [main 2] layer 1 gather (warp/dst), fp16 out ----------------
__global__ void gat1_gather_kernel(const float* __restrict__ b1,
                                   const float* __restrict__ gamma,
                                   const float* __restrict__ beta,
                                   const float* __restrict__ mean,
                                   const float* __restrict__ var, int n) {
    int w = (blockIdx.x * blockDim.x + threadIdx.x) >> 5;
    int lane = threadIdx.x & 31;
    if (w >= n) return;
    int h = lane >> 3;
    int beg = g_row[w], end = g_row[w + 1];
    float ad = g_ad1[w * 4 + h];
    float ub = lrelu(g_gmax[h] + g_gmax[4 + h]);

    float4 acc = make_float4(0.f, 0.f, 0.f, 0.f);
    float ssum = 0.f;
    int cb = lane * 4;
    int e = beg;
    for (; e + 8 <= end; e += 8) {
        int sv[8];
#pragma unroll
        for (int j = 0; j < 8; j++) sv[j] = __ldg(&g_csrc[e + j]);
        float av[8];
#pragma unroll
        for (int j = 0; j < 8; j++) av[j] = __ldg(&g_as1[sv[j] * 4 + h]);
        uint2 hv[8];
#pragma unroll
        for (int j = 0; j < 8; j++) hv[j] = __ldg((const uint2*)&g_h1h[sv[j] * 128 + cb]);
#pragma unroll
        for (int j = 0; j < 8; j++) {
            float p = __expf(lrelu(av[j] + ad) - ub);
            ssum += p;
            float2 f01 = __half22float2(*(__half2*)&hv[j].x);
            float2 f23 = __half22float2(*(__half2*)&hv[j].y);
            acc.x += p * f01.x;
            acc.y += p * f01.y;
            acc.z += p * f23.x;
            acc.w += p * f23.y;
        }
    }
    for (; e + 4 <= end; e += 4) {
        int sv[4];
#pragma unroll
        for (int j = 0; j < 4; j++) sv[j] = __ldg(&g_csrc[e + j]);
        float av[4];
#pragma unroll
        for (int j = 0; j < 4; j++) av[j] = __ldg(&g_as1[sv[j] * 4 + h]);
        uint2 hv[4];
#pragma unroll
        for (int j = 0; j < 4; j++) hv[j] = __ldg((const uint2*)&g_h1h[sv[j] * 128 + cb]);
#pragma unroll
        for (int j = 0; j < 4; j++) {
            float p = __expf(lrelu(av[j] + ad) - ub);
            ssum += p;
            float2 f01 = __half22float2(*(__half2*)&hv[j].x);
            float2 f23 = __half22float2(*(__half2*)&hv[j].y);
            acc.x += p * f01.x;
            acc.y += p * f01.y;
            acc.z += p * f23.x;
            acc.w += p * f23.y;
        }
    }
    for (; e < end; e++) {
        int s0 = __ldg(&g_csrc[e]);
        float a0 = __ldg(&g_as1[s0 * 4 + h]);
        uint2 v0 = __ldg((const uint2*)&g_h1h[s0 * 128 + cb]);
        float p0 = __expf(lrelu(a0 + ad) - ub);
        ssum += p0;
        float2 f01 = __half22float2(*(__half2*)&v0.x);
        float2 f23 = __half22float2(*(__half2*)&v0.y);
        acc.x += p0 * f01.x;
        acc.y += p0 * f01.y;
        acc.z += p0 * f23.x;
        acc.w += p0 * f23.y;
    }

    float inv = 1.f / ssum;
    float o[4];
#pragma unroll
    for (int j = 0; j < 4; j++) {
        float v = ((&acc.x)[j]) * inv + b1[cb + j];
        v = gamma[cb + j] * (v - mean[cb + j]) * rsqrtf(var[cb + j] + EPS_BN) + beta[cb + j];
        o[j] = fmaxf(v, 0.f);
    }
    __half2 p0 = __float22half2_rn(make_float2(o[0], o[1]));
    __half2 p1 = __float22half2_rn(make_float2(o[2], o[3]));
    uint2 pk;
    pk.x = *(unsigned*)&p0;
    pk.y = *(unsigned*)&p1;
    *(uint2*)&g_acch[w * 128 + cb] = pk;
}

// ---------------- [main 3] layer 2 GEMM (tc tf32, fp16 A in): h2 -> fp16, scores, gmax ----------------
__global__ void __launch_bounds__(256) gemm2_tc_kernel(
    const float* __restrict__ W,
    const float* __restrict__ att_s, const float* __restrict__ att_d, int n) {
    __shared__ float sA[128][36];
    __shared__ float sW[32][72];

    int tid = threadIdx.x;
    int warp = tid >> 5, lane = tid & 31;
    int gid = lane >> 2, tig = lane & 3;
    int row0 = blockIdx.x * 128;

    float acc[8][4];
#pragma unroll
    for (int nt = 0; nt < 8; nt++)
#pragma unroll
        for (int r = 0; r < 4; r++) acc[nt][r] = 0.f;

    for (int kc = 0; kc < 4; kc++) {
        int k0 = kc * 32;
        __syncthreads();
#pragma unroll
        for (int rep = 0; rep < 4; rep++) {
            int f = tid + rep * 256;
            int r = f >> 3, c4 = f & 7;
            int gr = row0 + r;
            float4 t = make_float4(0.f, 0.f, 0.f, 0.f);
            if (gr < n) {
                uint2 hv = *(const uint2*)&g_acch[gr * 128 + k0 + c4 * 4];
                float2 f01 = __half22float2(*(__half2*)&hv.x);
                float2 f23 = __half22float2(*(__half2*)&hv.y);
                t = make_float4(f2tf32(f01.x), f2tf32(f01.y), f2tf32(f23.x), f2tf32(f23.y));
            }
            *(float4*)&sA[r][c4 * 4] = t;
        }
#pragma unroll
        for (int rep = 0; rep < 2; rep++) {
            int f = tid + rep * 256;
            int kr = f >> 4, c4 = f & 15;
            float4 v = *(const float4*)&W[(k0 + kr) * 64 + c4 * 4];
            float4 t = make_float4(f2tf32(v.x), f2tf32(v.y), f2tf32(v.z), f2tf32(v.w));
            *(float4*)&sW[kr][c4 * 4] = t;
        }
        __syncthreads();
#pragma unroll
        for (int ks = 0; ks < 4; ks++) {
            int kk = ks * 8;
            unsigned a[4], b[8][2];
            {
                int r = warp * 16 + gid;
                a[0] = __float_as_uint(sA[r][kk + tig]);
                a[1] = __float_as_uint(sA[r + 8][kk + tig]);
                a[2] = __float_as_uint(sA[r][kk + tig + 4]);
                a[3] = __float_as_uint(sA[r + 8][kk + tig + 4]);
            }
#pragma unroll
            for (int nt = 0; nt < 8; nt++) {
                int c = nt * 8 + gid;
                b[nt][0] = __float_as_uint(sW[kk + tig][c]);
                b[nt][1] = __float_as_uint(sW[kk + tig + 4][c]);
            }
#pragma unroll
            for (int nt = 0; nt < 8; nt++) mma_tf32(acc[nt], a, b[nt]);
        }
    }

    float asr[16], adr[16];
#pragma unroll
    for (int nt = 0; nt < 8; nt++) {
        int c = nt * 8 + tig * 2;
        asr[nt * 2 + 0] = att_s[c];
        asr[nt * 2 + 1] = att_s[c + 1];
        adr[nt * 2 + 0] = att_d[c];
        adr[nt * 2 + 1] = att_d[c + 1];
    }
    float mxs = __int_as_float(0xff800000), mxd = __int_as_float(0xff800000);
#pragma unroll
    for (int half = 0; half < 2; half++) {
        int r = row0 + warp * 16 + gid + half * 8;
        float sa = 0.f, sd = 0.f;
        if (r < n) {
#pragma unroll
            for (int nt = 0; nt < 8; nt++) {
                float c0 = acc[nt][half * 2 + 0];
                float c1 = acc[nt][half * 2 + 1];
                int col = nt * 8 + tig * 2;
                *(__half2*)&g_h1h[r * 64 + col] =
                    __float22half2_rn(make_float2(c0, c1));
                sa += c0 * asr[nt * 2] + c1 * asr[nt * 2 + 1];
                sd += c0 * adr[nt * 2] + c1 * adr[nt * 2 + 1];
            }
        }
        sa += __shfl_xor_sync(0xffffffffu, sa, 1);
        sa += __shfl_xor_sync(0xffffffffu, sa, 2);
        sd += __shfl_xor_sync(0xffffffffu, sd, 1);
        sd += __shfl_xor_sync(0xffffffffu, sd, 2);
        if (r < n) {
            mxs = fmaxf(mxs, sa);
            mxd = fmaxf(mxd, sd);
            if (tig == 0) {
                g_as2[r] = sa;
                g_ad2[r] = sd;
            }
        }
    }
#pragma unroll
    for (int off = 16; off > 0; off >>= 1) {
        mxs = fmaxf(mxs, __shfl_xor_sync(0xffffffffu, mxs, off));
        mxd = fmaxf(mxd, __shfl_xor_sync(0xffffffffu, mxd, off));
    }
    if (lane == 0) {
        atomicMaxF(&g_gmax2[0], mxs);
        atomicMaxF(&g_gmax2[1], mxd);
    }
}

// ---------------- [main 4] layer 2 gather (warp/dst), fp16 h ----------------
__global__ void gat2_gather_kernel(float* __restrict__ out,
                                   const float* __restrict__ b2,
                                   const float* __restrict__ gamma,
                                   const float* __restrict__ beta,
                                   const float* __restrict__ mean,
                                   const float* __restrict__ var, int n) {
    int w = (blockIdx.x * blockDim.x + threadIdx.x) >> 5;
    int lane = threadIdx.x & 31;
    if (w >= n) return;
    int beg = g_row[w], end = g_row[w + 1];
    float ad = g_ad2[w];
    float ub = lrelu(g_gmax2[0] + g_gmax2[1]);

    float2 acc = make_float2(0.f, 0.f);
    float ssum = 0.f;
    int cb = lane * 2;
    int e = beg;
    for (; e + 8 <= end; e += 8) {
        int sv[8];
#pragma unroll
        for (int j = 0; j < 8; j++) sv[j] = __ldg(&g_csrc[e + j]);
        float av[8];
#pragma unroll
        for (int j = 0; j < 8; j++) av[j] = __ldg(&g_as2[sv[j]]);
        unsigned hv[8];
#pragma unroll
        for (int j = 0; j < 8; j++) hv[j] = __ldg((const unsigned*)&g_h1h[sv[j] * 64 + cb]);
#pragma unroll
        for (int j = 0; j < 8; j++) {
            float p = __expf(lrelu(av[j] + ad) - ub);
            ssum += p;
            float2 f = __half22float2(*(__half2*)&hv[j]);
            acc.x += p * f.x;
            acc.y += p * f.y;
        }
    }
    for (; e + 4 <= end; e += 4) {
        int sv[4];
#pragma unroll
        for (int j = 0; j < 4; j++) sv[j] = __ldg(&g_csrc[e + j]);
        float av[4];
#pragma unroll
        for (int j = 0; j < 4; j++) av[j] = __ldg(&g_as2[sv[j]]);
        unsigned hv[4];
#pragma unroll
        for (int j = 0; j < 4; j++) hv[j] = __ldg((const unsigned*)&g_h1h[sv[j] * 64 + cb]);
#pragma unroll
        for (int j = 0; j < 4; j++) {
            float p = __expf(lrelu(av[j] + ad) - ub);
            ssum += p;
            float2 f = __half22float2(*(__half2*)&hv[j]);
            acc.x += p * f.x;
            acc.y += p * f.y;
        }
    }
    for (; e < end; e++) {
        int s0 = __ldg(&g_csrc[e]);
        float a0 = __ldg(&g_as2[s0]);
        unsigned v0 = __ldg((const unsigned*)&g_h1h[s0 * 64 + cb]);
        float p0 = __expf(lrelu(a0 + ad) - ub);
        ssum += p0;
        float2 f = __half22float2(*(__half2*)&v0);
        acc.x += p0 * f.x;
        acc.y += p0 * f.y;
    }

    float inv = 1.f / ssum;
    float vx = acc.x * inv + b2[cb];
    float vy = acc.y * inv + b2[cb + 1];
    vx = gamma[cb] * (vx - mean[cb]) * rsqrtf(var[cb] + EPS_BN) + beta[cb];
    vy = gamma[cb + 1] * (vy - mean[cb + 1]) * rsqrtf(var[cb + 1] + EPS_BN) + beta[cb + 1];
    *(float2*)&out[w * 64 + cb] = make_float2(vx, vy);
}

// ---------------- launcher: fork CSR || gemm1; sequential post-join chain ----------------
extern "C" void kernel_launch(void* const* d_in, const int* in_sizes, int n_in,
                              void* d_out, int out_size) {
    const float* x        = (const float*)d_in[0];
    const int*   ei       = (const int*)d_in[1];   // int32 (JAX demotes int64)
    const float* W1       = (const float*)d_in[2];
    const float* att_src1 = (const float*)d_in[3];
    const float* att_dst1 = (const float*)d_in[4];
    const float* b1       = (const float*)d_in[5];
    const float* bn1_g    = (const float*)d_in[6];
    const float* bn1_b    = (const float*)d_in[7];
    const float* bn1_m    = (const float*)d_in[8];
    const float* bn1_v    = (const float*)d_in[9];
    const float* W2       = (const float*)d_in[10];
    const float* att_src2 = (const float*)d_in[11];
    const float* att_dst2 = (const float*)d_in[12];
    const float* b2       = (const float*)d_in[13];
    const float* bn2_g    = (const float*)d_in[14];
    const float* bn2_b    = (const float*)d_in[15];
    const float* bn2_m    = (const float*)d_in[16];
    const float* bn2_v    = (const float*)d_in[17];
    float* out = (float*)d_out;

    int n = in_sizes[0] / 128;
    int E = in_sizes[1] / 2;
    int nb = (n + SCAN_CHUNK - 1) / SCAN_CHUNK;

    const int B = 256;

    static cudaStream_t side = nullptr;
    static cudaEvent_t evFork = nullptr, evJoin = nullptr;
    if (side == nullptr) {
        cudaStreamCreateWithFlags(&side, cudaStreamNonBlocking);
        cudaEventCreateWithFlags(&evFork, cudaEventDisableTiming);
        cudaEventCreateWithFlags(&evJoin, cudaEventDisableTiming);
    }

    // ---- fork: CSR build on side stream, gemm1 on main stream ----
    cudaEventRecord(evFork, 0);
    cudaStreamWaitEvent(side, evFork, 0);

    hist_kernel<<<(E + B - 1) / B, B, 0, side>>>(ei, E);
    scan_part_kernel<<<nb, 256, 0, side>>>(n);
    scan_down_kernel<<<nb, 256, 0, side>>>(n, nb);
    scatter_kernel<<<(E + B - 1) / B, B, 0, side>>>(ei, E);
    cudaEventRecord(evJoin, side);

    gemm1_tc_kernel<<<(n + 127) / 128, 256>>>(x, W1, att_src1, att_dst1, n);

    // ---- join CSR, then the sequential chain ----
    cudaStreamWaitEvent(0, evJoin, 0);
    gat1_gather_kernel<<<(n * 32 + B - 1) / B, B>>>(b1, bn1_g, bn1_b, bn1_m, bn1_v, n);
    gemm2_tc_kernel<<<(n + 127) / 128, 256>>>(W2, att_src2, att_dst2, n);
    gat2_gather_kernel<<<(n * 32 + B - 1) / B, B>>>(out, b2, bn2_g, bn2_b, bn2_m, bn2_v, n);
}

// round 16
// speedup vs baseline: 1.1722x; 1.0010x over previous
#include <cuda_runtime.h>
#include <cuda_fp16.h>

#define NMAX 100000
#define EMAX 1600000
#define ETMAX (EMAX + NMAX)
#define SCAN_CHUNK 1024
#define SCAN_BLOCKS ((NMAX + SCAN_CHUNK - 1) / SCAN_CHUNK)

// ---------------- scratch (static device globals; no allocation) ----------------
__device__ __align__(16) __half g_h1h[NMAX * 128];  // layer1 h fp16; reused for layer2 h fp16 (stride 64)
__device__ __align__(16) __half g_acch[NMAX * 128]; // layer1 output (post BN/ReLU), fp16
__device__ __align__(16) float g_as1[NMAX * 4];
__device__ __align__(16) float g_ad1[NMAX * 4];
__device__ __align__(16) float g_as2[NMAX];
__device__ __align__(16) float g_ad2[NMAX];
__device__ float g_gmax[8];    // [0..3]=max as1 per head, [4..7]=max ad1 per head
__device__ float g_gmax2[2];   // [0]=max as2, [1]=max ad2
__device__ int g_cnt[NMAX];    // INVARIANT: zero on entry (re-zeroed by scan_down)
__device__ int g_rank[EMAX];   // per-edge rank within its dst (from hist)
__device__ int g_row[NMAX + 1];
__device__ int g_csrc[ETMAX];
__device__ int g_part[SCAN_BLOCKS + 1];

#define NEG_SLOPE 0.2f
#define EPS_BN 1e-5f

__device__ __forceinline__ float lrelu(float v) {
    return v > 0.f ? v : NEG_SLOPE * v;
}

__device__ __forceinline__ void atomicMaxF(float* addr, float v) {
    if (v >= 0.f) atomicMax((int*)addr, __float_as_int(v));
    else          atomicMin((unsigned int*)addr, __float_as_uint(v));
}

__device__ __forceinline__ unsigned pack_half2(float a, float b) {
    __half2 h = __floats2half2_rn(a, b);
    return *(unsigned*)&h;
}

// m16n8k16 fp16 MMA, fp32 accumulate. C layout identical to tf32 m16n8k8.
__device__ __forceinline__ void mma_f16(float* c, const unsigned* a, const unsigned* b) {
    asm volatile(
        "mma.sync.aligned.m16n8k16.row.col.f32.f16.f16.f32 "
        "{%0,%1,%2,%3}, {%4,%5,%6,%7}, {%8,%9}, {%0,%1,%2,%3};\n"
        : "+f"(c[0]), "+f"(c[1]), "+f"(c[2]), "+f"(c[3])
        : "r"(a[0]), "r"(a[1]), "r"(a[2]), "r"(a[3]), "r"(b[0]), "r"(b[1]));
}

// ---------------- [side 1] histogram (unroll x4) + per-edge rank + gmax init ----------------
__global__ void hist_kernel(const int* __restrict__ ei, int E, int T) {
    if (blockIdx.x == 0 && threadIdx.x < 10) {
        float ninf = __int_as_float(0xff800000);
        if (threadIdx.x < 8) g_gmax[threadIdx.x] = ninf;
        else                 g_gmax2[threadIdx.x - 8] = ninf;
    }
    int t = blockIdx.x * blockDim.x + threadIdx.x;
    if (t >= T) return;
#pragma unroll
    for (int j = 0; j < 4; j++) {
        int e = t + j * T;
        if (e < E) g_rank[e] = atomicAdd(&g_cnt[__ldg(&ei[E + e])], 1);
    }
}

// ---------------- [side 2] per-block partial sums (+1 self-loop per node) ----------------
__global__ void scan_part_kernel(int n) {
    __shared__ int sh[256];
    int blk = blockIdx.x;
    int t = threadIdx.x;
    int base = blk * SCAN_CHUNK + t * 4;
    int s = 0;
#pragma unroll
    for (int i = 0; i < 4; i++) {
        int idx = base + i;
        if (idx < n) s += g_cnt[idx] + 1;   // +1 = self-loop
    }
    sh[t] = s;
    __syncthreads();
#pragma unroll
    for (int off = 128; off > 0; off >>= 1) {
        if (t < off) sh[t] += sh[t + off];
        __syncthreads();
    }
    if (t == 0) g_part[blk] = sh[0];
}

// ---------------- [side 3] down-sweep: top scan + local scan + self-loop write + re-zero ----------------
__global__ void scan_down_kernel(int n, int nb) {
    __shared__ int sp[128];
    __shared__ int sh[256];
    int blk = blockIdx.x;
    int t = threadIdx.x;

    if (t < 128) sp[t] = (t < nb) ? g_part[t] : 0;
    __syncthreads();
    for (int off = 1; off < 128; off <<= 1) {
        int u = 0;
        if (t < 128 && t >= off) u = sp[t - off];
        __syncthreads();
        if (t < 128) sp[t] += u;
        __syncthreads();
    }
    if (blk == 0 && t == 0) g_row[n] = sp[nb - 1];
    int blockoff = sp[blk] - g_part[blk];

    int base = blk * SCAN_CHUNK + t * 4;
    int v[4];
    int s = 0;
#pragma unroll
    for (int i = 0; i < 4; i++) {
        int idx = base + i;
        v[i] = (idx < n) ? (g_cnt[idx] + 1) : 0;
        s += v[i];
    }
    sh[t] = s;
    __syncthreads();
    for (int off = 1; off < 256; off <<= 1) {
        int u = (t >= off) ? sh[t - off] : 0;
        __syncthreads();
        sh[t] += u;
        __syncthreads();
    }
    int running = sh[t] - s + blockoff;
#pragma unroll
    for (int i = 0; i < 4; i++) {
        int idx = base + i;
        if (idx < n) {
            g_row[idx] = running;
            g_csrc[running] = idx;   // self-loop src at row start
            g_cnt[idx] = 0;          // restore invariant for next replay
            running += v[i];
        }
    }
}

// ---------------- [side 4] deterministic scatter via per-edge rank (unroll x2) ----------------
__global__ void scatter_kernel(const int* __restrict__ ei, int E, int T) {
    int t = blockIdx.x * blockDim.x + threadIdx.x;
    if (t >= T) return;
#pragma unroll
    for (int j = 0; j < 2; j++) {
        int e = t + j * T;
        if (e < E) {
            int src = __ldg(&ei[e]);
            int dst = __ldg(&ei[E + e]);
            int rank = g_rank[e];
            g_csrc[__ldg(&g_row[dst]) + 1 + rank] = src;
        }
    }
}

// ---------------- [main 1] layer 1 GEMM (fp16 HMMA) + fused scores + gmax ----------------
// Block 128x128, 8 warps (2M x 4N), warp tile 64x32, BK=32 (2 x k16 steps).
__global__ void __launch_bounds__(256) gemm1_tc_kernel(
    const float* __restrict__ A, const float* __restrict__ W,
    const float* __restrict__ att_s, const float* __restrict__ att_d, int n) {
    __shared__ unsigned sAh[128][20];   // [row][k2] packed half2 (k2=0..15 used)
    __shared__ unsigned sWt[128][21];   // [col][k2] packed half2

    int tid = threadIdx.x;
    int warp = tid >> 5, lane = tid & 31;
    int gid = lane >> 2, tig = lane & 3;
    int mwarp = warp >> 2, nwarp = warp & 3;
    int row0 = blockIdx.x * 128;

    float acc[4][4][4];
#pragma unroll
    for (int mt = 0; mt < 4; mt++)
#pragma unroll
        for (int nt = 0; nt < 4; nt++)
#pragma unroll
            for (int r = 0; r < 4; r++) acc[mt][nt][r] = 0.f;

    for (int kc = 0; kc < 4; kc++) {
        int k0 = kc * 32;
        __syncthreads();
        // A chunk: 128 rows x 32 k (8 float4 per row), convert to packed half2
#pragma unroll
        for (int rep = 0; rep < 4; rep++) {
            int f = tid + rep * 256;
            int r = f >> 3, c4 = f & 7;
            int gr = row0 + r;
            float4 v = make_float4(0.f, 0.f, 0.f, 0.f);
            if (gr < n) v = *(const float4*)&A[gr * 128 + k0 + c4 * 4];
            sAh[r][c4 * 2 + 0] = pack_half2(v.x, v.y);
            sAh[r][c4 * 2 + 1] = pack_half2(v.z, v.w);
        }
        // W chunk: transpose-pack along k: sWt[c][k2] = (W[2k2][c], W[2k2+1][c])
#pragma unroll
        for (int rep = 0; rep < 8; rep++) {
            int f = tid + rep * 256;
            int c = f & 127, k2 = f >> 7;
            float w0 = __ldg(&W[(k0 + 2 * k2) * 128 + c]);
            float w1 = __ldg(&W[(k0 + 2 * k2 + 1) * 128 + c]);
            sWt[c][k2] = pack_half2(w0, w1);
        }
        __syncthreads();
#pragma unroll
        for (int ks = 0; ks < 2; ks++) {
            int kb = ks * 8;
            unsigned b[4][2], a[4][4];
#pragma unroll
            for (int nt = 0; nt < 4; nt++) {
                int c = nwarp * 32 + nt * 8 + gid;
                b[nt][0] = sWt[c][kb + tig];
                b[nt][1] = sWt[c][kb + tig + 4];
            }
#pragma unroll
            for (int mt = 0; mt < 4; mt++) {
                int r = mwarp * 64 + mt * 16 + gid;
                a[mt][0] = sAh[r][kb + tig];
                a[mt][1] = sAh[r + 8][kb + tig];
                a[mt][2] = sAh[r][kb + tig + 4];
                a[mt][3] = sAh[r + 8][kb + tig + 4];
            }
#pragma unroll
            for (int mt = 0; mt < 4; mt++)
#pragma unroll
                for (int nt = 0; nt < 4; nt++) mma_f16(acc[mt][nt], a[mt], b[nt]);
        }
    }

    // epilogue: fp16 h store + fused per-head scores (head == nwarp) + gmax
    float asr[8], adr[8];
#pragma unroll
    for (int nt = 0; nt < 4; nt++) {
        int c = nwarp * 32 + nt * 8 + tig * 2;
        asr[nt * 2 + 0] = att_s[c];
        asr[nt * 2 + 1] = att_s[c + 1];
        adr[nt * 2 + 0] = att_d[c];
        adr[nt * 2 + 1] = att_d[c + 1];
    }
    float mxs = __int_as_float(0xff800000), mxd = __int_as_float(0xff800000);
#pragma unroll
    for (int mt = 0; mt < 4; mt++) {
#pragma unroll
        for (int half = 0; half < 2; half++) {
            int r = row0 + mwarp * 64 + mt * 16 + gid + half * 8;
            float sa = 0.f, sd = 0.f;
            if (r < n) {
#pragma unroll
                for (int nt = 0; nt < 4; nt++) {
                    float c0 = acc[mt][nt][half * 2 + 0];
                    float c1 = acc[mt][nt][half * 2 + 1];
                    int col = nwarp * 32 + nt * 8 + tig * 2;
                    *(__half2*)&g_h1h[r * 128 + col] =
                        __float22half2_rn(make_float2(c0, c1));
                    sa += c0 * asr[nt * 2] + c1 * asr[nt * 2 + 1];
                    sd += c0 * adr[nt * 2] + c1 * adr[nt * 2 + 1];
                }
            }
            sa += __shfl_xor_sync(0xffffffffu, sa, 1);
            sa += __shfl_xor_sync(0xffffffffu, sa, 2);
            sd += __shfl_xor_sync(0xffffffffu, sd, 1);
            sd += __shfl_xor_sync(0xffffffffu, sd, 2);
            if (r < n) {
                mxs = fmaxf(mxs, sa);
                mxd = fmaxf(mxd, sd);
                if (tig == 0) {
                    g_as1[r * 4 + nwarp] = sa;
                    g_ad1[r * 4 + nwarp] = sd;
                }
            }
        }
    }
#pragma unroll
    for (int off = 16; off > 0; off >>= 1) {
        mxs = fmaxf(mxs, __shfl_xor_sync(0xffffffffu, mxs, off));
        mxd = fmaxf(mxd, __shfl_xor_sync(0xffffffffu, mxd, off));
    }
    if (lane == 0) {
        atomicMaxF(&g_gmax[nwarp], mxs);
        atomicMaxF(&g_gmax[4 + nwarp], mxd);
    }
}

// ---------------- [main 2] layer 1 gather (warp/dst), fp16 out ----------------
__global__ void gat1_gather_kernel(const float* __restrict__ b1,
                                   const float* __restrict__ gamma,
                                   const float* __restrict__ beta,
                                   const float* __restrict__ mean,
                                   const float* __restrict__ var, int n) {
    int w = (blockIdx.x * blockDim.x + threadIdx.x) >> 5;
    int lane = threadIdx.x & 31;
    if (w >= n) return;
    int h = lane >> 3;
    int beg = g_row[w], end = g_row[w + 1];
    float ad = g_ad1[w * 4 + h];
    float ub = lrelu(g_gmax[h] + g_gmax[4 + h]);

    float4 acc = make_float4(0.f, 0.f, 0.f, 0.f);
    float ssum = 0.f;
    int cb = lane * 4;
    int e = beg;
    for (; e + 8 <= end; e += 8) {
        int sv[8];
#pragma unroll
        for (int j = 0; j < 8; j++) sv[j] = __ldg(&g_csrc[e + j]);
        float av[8];
#pragma unroll
        for (int j = 0; j < 8; j++) av[j] = __ldg(&g_as1[sv[j] * 4 + h]);
        uint2 hv[8];
#pragma unroll
        for (int j = 0; j < 8; j++) hv[j] = __ldg((const uint2*)&g_h1h[sv[j] * 128 + cb]);
#pragma unroll
        for (int j = 0; j < 8; j++) {
            float p = __expf(lrelu(av[j] + ad) - ub);
            ssum += p;
            float2 f01 = __half22float2(*(__half2*)&hv[j].x);
            float2 f23 = __half22float2(*(__half2*)&hv[j].y);
            acc.x += p * f01.x;
            acc.y += p * f01.y;
            acc.z += p * f23.x;
            acc.w += p * f23.y;
        }
    }
    for (; e + 4 <= end; e += 4) {
        int sv[4];
#pragma unroll
        for (int j = 0; j < 4; j++) sv[j] = __ldg(&g_csrc[e + j]);
        float av[4];
#pragma unroll
        for (int j = 0; j < 4; j++) av[j] = __ldg(&g_as1[sv[j] * 4 + h]);
        uint2 hv[4];
#pragma unroll
        for (int j = 0; j < 4; j++) hv[j] = __ldg((const uint2*)&g_h1h[sv[j] * 128 + cb]);
#pragma unroll
        for (int j = 0; j < 4; j++) {
            float p = __expf(lrelu(av[j] + ad) - ub);
            ssum += p;
            float2 f01 = __half22float2(*(__half2*)&hv[j].x);
            float2 f23 = __half22float2(*(__half2*)&hv[j].y);
            acc.x += p * f01.x;
            acc.y += p * f01.y;
            acc.z += p * f23.x;
            acc.w += p * f23.y;
        }
    }
    for (; e < end; e++) {
        int s0 = __ldg(&g_csrc[e]);
        float a0 = __ldg(&g_as1[s0 * 4 + h]);
        uint2 v0 = __ldg((const uint2*)&g_h1h[s0 * 128 + cb]);
        float p0 = __expf(lrelu(a0 + ad) - ub);
        ssum += p0;
        float2 f01 = __half22float2(*(__half2*)&v0.x);
        float2 f23 = __half22float2(*(__half2*)&v0.y);
        acc.x += p0 * f01.x;
        acc.y += p0 * f01.y;
        acc.z += p0 * f23.x;
        acc.w += p0 * f23.y;
    }

    float inv = 1.f / ssum;
    float o[4];
#pragma unroll
    for (int j = 0; j < 4; j++) {
        float v = ((&acc.x)[j]) * inv + b1[cb + j];
        v = gamma[cb + j] * (v - mean[cb + j]) * rsqrtf(var[cb + j] + EPS_BN) + beta[cb + j];
        o[j] = fmaxf(v, 0.f);
    }
    __half2 p0 = __float22half2_rn(make_float2(o[0], o[1]));
    __half2 p1 = __float22half2_rn(make_float2(o[2], o[3]));
    uint2 pk;
    pk.x = *(unsigned*)&p0;
    pk.y = *(unsigned*)&p1;
    *(uint2*)&g_acch[w * 128 + cb] = pk;
}

// ---------------- [main 3] layer 2 GEMM (fp16 HMMA, fp16 A in): h2 -> fp16, scores, gmax ----------------
// Block 128x64, 8 warps all M, warp tile 16x64, BK=32.
__global__ void __launch_bounds__(256) gemm2_tc_kernel(
    const float* __restrict__ W,
    const float* __restrict__ att_s, const float* __restrict__ att_d, int n) {
    __shared__ unsigned sAh[128][20];
    __shared__ unsigned sWt[64][21];

    int tid = threadIdx.x;
    int warp = tid >> 5, lane = tid & 31;
    int gid = lane >> 2, tig = lane & 3;
    int row0 = blockIdx.x * 128;

    float acc[8][4];
#pragma unroll
    for (int nt = 0; nt < 8; nt++)
#pragma unroll
        for (int r = 0; r < 4; r++) acc[nt][r] = 0.f;

    for (int kc = 0; kc < 4; kc++) {
        int k0 = kc * 32;
        __syncthreads();
        // A chunk: already fp16, pure repack (uint2 = 4 halves = 2 packed pairs)
#pragma unroll
        for (int rep = 0; rep < 4; rep++) {
            int f = tid + rep * 256;
            int r = f >> 3, c4 = f & 7;
            int gr = row0 + r;
            uint2 hv = make_uint2(0u, 0u);
            if (gr < n) hv = *(const uint2*)&g_acch[gr * 128 + k0 + c4 * 4];
            sAh[r][c4 * 2 + 0] = hv.x;
            sAh[r][c4 * 2 + 1] = hv.y;
        }
        // W chunk: 16 k2 x 64 c = 1024
#pragma unroll
        for (int rep = 0; rep < 4; rep++) {
            int f = tid + rep * 256;
            int c = f & 63, k2 = f >> 6;
            float w0 = __ldg(&W[(k0 + 2 * k2) * 64 + c]);
            float w1 = __ldg(&W[(k0 + 2 * k2 + 1) * 64 + c]);
            sWt[c][k2] = pack_half2(w0, w1);
        }
        __syncthreads();
#pragma unroll
        for (int ks = 0; ks < 2; ks++) {
            int kb = ks * 8;
            unsigned a[4], b[8][2];
            {
                int r = warp * 16 + gid;
                a[0] = sAh[r][kb + tig];
                a[1] = sAh[r + 8][kb + tig];
                a[2] = sAh[r][kb + tig + 4];
                a[3] = sAh[r + 8][kb + tig + 4];
            }
#pragma unroll
            for (int nt = 0; nt < 8; nt++) {
                int c = nt * 8 + gid;
                b[nt][0] = sWt[c][kb + tig];
                b[nt][1] = sWt[c][kb + tig + 4];
            }
#pragma unroll
            for (int nt = 0; nt < 8; nt++) mma_f16(acc[nt], a, b[nt]);
        }
    }

    float asr[16], adr[16];
#pragma unroll
    for (int nt = 0; nt < 8; nt++) {
        int c = nt * 8 + tig * 2;
        asr[nt * 2 + 0] = att_s[c];
        asr[nt * 2 + 1] = att_s[c + 1];
        adr[nt * 2 + 0] = att_d[c];
        adr[nt * 2 + 1] = att_d[c + 1];
    }
    float mxs = __int_as_float(0xff800000), mxd = __int_as_float(0xff800000);
#pragma unroll
    for (int half = 0; half < 2; half++) {
        int r = row0 + warp * 16 + gid + half * 8;
        float sa = 0.f, sd = 0.f;
        if (r < n) {
#pragma unroll
            for (int nt = 0; nt < 8; nt++) {
                float c0 = acc[nt][half * 2 + 0];
                float c1 = acc[nt][half * 2 + 1];
                int col = nt * 8 + tig * 2;
                *(__half2*)&g_h1h[r * 64 + col] =
                    __float22half2_rn(make_float2(c0, c1));
                sa += c0 * asr[nt * 2] + c1 * asr[nt * 2 + 1];
                sd += c0 * adr[nt * 2] + c1 * adr[nt * 2 + 1];
            }
        }
        sa += __shfl_xor_sync(0xffffffffu, sa, 1);
        sa += __shfl_xor_sync(0xffffffffu, sa, 2);
        sd += __shfl_xor_sync(0xffffffffu, sd, 1);
        sd += __shfl_xor_sync(0xffffffffu, sd, 2);
        if (r < n) {
            mxs = fmaxf(mxs, sa);
            mxd = fmaxf(mxd, sd);
            if (tig == 0) {
                g_as2[r] = sa;
                g_ad2[r] = sd;
            }
        }
    }
#pragma unroll
    for (int off = 16; off > 0; off >>= 1) {
        mxs = fmaxf(mxs, __shfl_xor_sync(0xffffffffu, mxs, off));
        mxd = fmaxf(mxd, __shfl_xor_sync(0xffffffffu, mxd, off));
    }
    if (lane == 0) {
        atomicMaxF(&g_gmax2[0], mxs);
        atomicMaxF(&g_gmax2[1], mxd);
    }
}

// ---------------- [main 4] layer 2 gather (warp/dst), fp16 h ----------------
__global__ void gat2_gather_kernel(float* __restrict__ out,
                                   const float* __restrict__ b2,
                                   const float* __restrict__ gamma,
                                   const float* __restrict__ beta,
                                   const float* __restrict__ mean,
                                   const float* __restrict__ var, int n) {
    int w = (blockIdx.x * blockDim.x + threadIdx.x) >> 5;
    int lane = threadIdx.x & 31;
    if (w >= n) return;
    int beg = g_row[w], end = g_row[w + 1];
    float ad = g_ad2[w];
    float ub = lrelu(g_gmax2[0] + g_gmax2[1]);

    float2 acc = make_float2(0.f, 0.f);
    float ssum = 0.f;
    int cb = lane * 2;
    int e = beg;
    for (; e + 8 <= end; e += 8) {
        int sv[8];
#pragma unroll
        for (int j = 0; j < 8; j++) sv[j] = __ldg(&g_csrc[e + j]);
        float av[8];
#pragma unroll
        for (int j = 0; j < 8; j++) av[j] = __ldg(&g_as2[sv[j]]);
        unsigned hv[8];
#pragma unroll
        for (int j = 0; j < 8; j++) hv[j] = __ldg((const unsigned*)&g_h1h[sv[j] * 64 + cb]);
#pragma unroll
        for (int j = 0; j < 8; j++) {
            float p = __expf(lrelu(av[j] + ad) - ub);
            ssum += p;
            float2 f = __half22float2(*(__half2*)&hv[j]);
            acc.x += p * f.x;
            acc.y += p * f.y;
        }
    }
    for (; e + 4 <= end; e += 4) {
        int sv[4];
#pragma unroll
        for (int j = 0; j < 4; j++) sv[j] = __ldg(&g_csrc[e + j]);
        float av[4];
#pragma unroll
        for (int j = 0; j < 4; j++) av[j] = __ldg(&g_as2[sv[j]]);
        unsigned hv[4];
#pragma unroll
        for (int j = 0; j < 4; j++) hv[j] = __ldg((const unsigned*)&g_h1h[sv[j] * 64 + cb]);
#pragma unroll
        for (int j = 0; j < 4; j++) {
            float p = __expf(lrelu(av[j] + ad) - ub);
            ssum += p;
            float2 f = __half22float2(*(__half2*)&hv[j]);
            acc.x += p * f.x;
            acc.y += p * f.y;
        }
    }
    for (; e < end; e++) {
        int s0 = __ldg(&g_csrc[e]);
        float a0 = __ldg(&g_as2[s0]);
        unsigned v0 = __ldg((const unsigned*)&g_h1h[s0 * 64 + cb]);
        float p0 = __expf(lrelu(a0 + ad) - ub);
        ssum += p0;
        float2 f = __half22float2(*(__half2*)&v0);
        acc.x += p0 * f.x;
        acc.y += p0 * f.y;
    }

    float inv = 1.f / ssum;
    float vx = acc.x * inv + b2[cb];
    float vy = acc.y * inv + b2[cb + 1];
    vx = gamma[cb] * (vx - mean[cb]) * rsqrtf(var[cb] + EPS_BN) + beta[cb];
    vy = gamma[cb + 1] * (vy - mean[cb + 1]) * rsqrtf(var[cb + 1] + EPS_BN) + beta[cb + 1];
    *(float2*)&out[w * 64 + cb] = make_float2(vx, vy);
}

// ---------------- launcher: fork CSR || gemm1; sequential post-join chain ----------------
extern "C" void kernel_launch(void* const* d_in, const int* in_sizes, int n_in,
                              void* d_out, int out_size) {
    const float* x        = (const float*)d_in[0];
    const int*   ei       = (const int*)d_in[1];   // int32 (JAX demotes int64)
    const float* W1       = (const float*)d_in[2];
    const float* att_src1 = (const float*)d_in[3];
    const float* att_dst1 = (const float*)d_in[4];
    const float* b1       = (const float*)d_in[5];
    const float* bn1_g    = (const float*)d_in[6];
    const float* bn1_b    = (const float*)d_in[7];
    const float* bn1_m    = (const float*)d_in[8];
    const float* bn1_v    = (const float*)d_in[9];
    const float* W2       = (const float*)d_in[10];
    const float* att_src2 = (const float*)d_in[11];
    const float* att_dst2 = (const float*)d_in[12];
    const float* b2       = (const float*)d_in[13];
    const float* bn2_g    = (const float*)d_in[14];
    const float* bn2_b    = (const float*)d_in[15];
    const float* bn2_m    = (const float*)d_in[16];
    const float* bn2_v    = (const float*)d_in[17];
    float* out = (float*)d_out;

    int n = in_sizes[0] / 128;
    int E = in_sizes[1] / 2;
    int nb = (n + SCAN_CHUNK - 1) / SCAN_CHUNK;

    const int B = 256;

    static cudaStream_t side = nullptr;
    static cudaEvent_t evFork = nullptr, evJoin = nullptr;
    if (side == nullptr) {
        cudaStreamCreateWithFlags(&side, cudaStreamNonBlocking);
        cudaEventCreateWithFlags(&evFork, cudaEventDisableTiming);
        cudaEventCreateWithFlags(&evJoin, cudaEventDisableTiming);
    }

    // ---- fork: CSR build on side stream, gemm1 on main stream ----
    cudaEventRecord(evFork, 0);
    cudaStreamWaitEvent(side, evFork, 0);

    int Th = (E + 3) / 4;   // hist unroll x4
    int Ts = (E + 1) / 2;   // scatter unroll x2
    hist_kernel<<<(Th + B - 1) / B, B, 0, side>>>(ei, E, Th);
    scan_part_kernel<<<nb, 256, 0, side>>>(n);
    scan_down_kernel<<<nb, 256, 0, side>>>(n, nb);
    scatter_kernel<<<(Ts + B - 1) / B, B, 0, side>>>(ei, E, Ts);
    cudaEventRecord(evJoin, side);

    gemm1_tc_kernel<<<(n + 127) / 128, 256>>>(x, W1, att_src1, att_dst1, n);

    // ---- join CSR, then the sequential chain ----
    cudaStreamWaitEvent(0, evJoin, 0);
    gat1_gather_kernel<<<(n * 32 + B - 1) / B, B>>>(b1, bn1_g, bn1_b, bn1_m, bn1_v, n);
    gemm2_tc_kernel<<<(n + 127) / 128, 256>>>(W2, att_src2, att_dst2, n);
    gat2_gather_kernel<<<(n * 32 + B - 1) / B, B>>>(out, b2, bn2_g, bn2_b, bn2_m, bn2_v, n);
}

// round 17
// speedup vs baseline: 1.1736x; 1.0012x over previous
#include <cuda_runtime.h>
#include <cuda_fp16.h>

#define NMAX 100000
#define EMAX 1600000
#define ETMAX (EMAX + NMAX)
#define SCAN_CHUNK 1024
#define SCAN_BLOCKS ((NMAX + SCAN_CHUNK - 1) / SCAN_CHUNK)

// ---------------- scratch (static device globals; no allocation) ----------------
__device__ __align__(16) __half g_h1h[NMAX * 128];  // layer1 h fp16; reused for layer2 h fp16 (stride 64)
__device__ __align__(16) __half g_acch[NMAX * 128]; // layer1 output (post BN/ReLU), fp16
__device__ __align__(16) float g_as1[NMAX * 4];
__device__ __align__(16) float g_ad1[NMAX * 4];
__device__ __align__(16) float g_as2[NMAX];
__device__ __align__(16) float g_ad2[NMAX];
__device__ float g_gmax[8];    // [0..3]=max as1 per head, [4..7]=max ad1 per head
__device__ float g_gmax2[2];   // [0]=max as2, [1]=max ad2
__device__ int g_cnt[NMAX];    // INVARIANT: zero on entry (re-zeroed by scan_down)
__device__ int g_rank[EMAX];   // per-edge rank within its dst (from hist)
__device__ int g_row[NMAX + 1];
__device__ int g_csrc[ETMAX];
__device__ int g_part[SCAN_BLOCKS + 1];

#define NEG_SLOPE 0.2f
#define EPS_BN 1e-5f

__device__ __forceinline__ float lrelu(float v) {
    return v > 0.f ? v : NEG_SLOPE * v;
}

__device__ __forceinline__ void atomicMaxF(float* addr, float v) {
    if (v >= 0.f) atomicMax((int*)addr, __float_as_int(v));
    else          atomicMin((unsigned int*)addr, __float_as_uint(v));
}

__device__ __forceinline__ unsigned pack_half2(float a, float b) {
    __half2 h = __floats2half2_rn(a, b);
    return *(unsigned*)&h;
}

// m16n8k16 fp16 MMA, fp32 accumulate. C layout identical to tf32 m16n8k8.
__device__ __forceinline__ void mma_f16(float* c, const unsigned* a, const unsigned* b) {
    asm volatile(
        "mma.sync.aligned.m16n8k16.row.col.f32.f16.f16.f32 "
        "{%0,%1,%2,%3}, {%4,%5,%6,%7}, {%8,%9}, {%0,%1,%2,%3};\n"
        : "+f"(c[0]), "+f"(c[1]), "+f"(c[2]), "+f"(c[3])
        : "r"(a[0]), "r"(a[1]), "r"(a[2]), "r"(a[3]), "r"(b[0]), "r"(b[1]));
}

// ---------------- [side 1] histogram (unroll x4) + per-edge rank + gmax init ----------------
__global__ void hist_kernel(const int* __restrict__ ei, int E, int T) {
    if (blockIdx.x == 0 && threadIdx.x < 10) {
        float ninf = __int_as_float(0xff800000);
        if (threadIdx.x < 8) g_gmax[threadIdx.x] = ninf;
        else                 g_gmax2[threadIdx.x - 8] = ninf;
    }
    int t = blockIdx.x * blockDim.x + threadIdx.x;
    if (t >= T) return;
#pragma unroll
    for (int j = 0; j < 4; j++) {
        int e = t + j * T;
        if (e < E) g_rank[e] = atomicAdd(&g_cnt[__ldg(&ei[E + e])], 1);
    }
}

// ---------------- [side 2] per-block partial sums (+1 self-loop per node) ----------------
__global__ void scan_part_kernel(int n) {
    __shared__ int sh[256];
    int blk = blockIdx.x;
    int t = threadIdx.x;
    int base = blk * SCAN_CHUNK + t * 4;
    int s = 0;
#pragma unroll
    for (int i = 0; i < 4; i++) {
        int idx = base + i;
        if (idx < n) s += g_cnt[idx] + 1;   // +1 = self-loop
    }
    sh[t] = s;
    __syncthreads();
#pragma unroll
    for (int off = 128; off > 0; off >>= 1) {
        if (t < off) sh[t] += sh[t + off];
        __syncthreads();
    }
    if (t == 0) g_part[blk] = sh[0];
}

// ---------------- [side 3] down-sweep: top scan + local scan + self-loop write + re-zero ----------------
__global__ void scan_down_kernel(int n, int nb) {
    __shared__ int sp[128];
    __shared__ int sh[256];
    int blk = blockIdx.x;
    int t = threadIdx.x;

    if (t < 128) sp[t] = (t < nb) ? g_part[t] : 0;
    __syncthreads();
    for (int off = 1; off < 128; off <<= 1) {
        int u = 0;
        if (t < 128 && t >= off) u = sp[t - off];
        __syncthreads();
        if (t < 128) sp[t] += u;
        __syncthreads();
    }
    if (blk == 0 && t == 0) g_row[n] = sp[nb - 1];
    int blockoff = sp[blk] - g_part[blk];

    int base = blk * SCAN_CHUNK + t * 4;
    int v[4];
    int s = 0;
#pragma unroll
    for (int i = 0; i < 4; i++) {
        int idx = base + i;
        v[i] = (idx < n) ? (g_cnt[idx] + 1) : 0;
        s += v[i];
    }
    sh[t] = s;
    __syncthreads();
    for (int off = 1; off < 256; off <<= 1) {
        int u = (t >= off) ? sh[t - off] : 0;
        __syncthreads();
        sh[t] += u;
        __syncthreads();
    }
    int running = sh[t] - s + blockoff;
#pragma unroll
    for (int i = 0; i < 4; i++) {
        int idx = base + i;
        if (idx < n) {
            g_row[idx] = running;
            g_csrc[running] = idx;   // self-loop src at row start
            g_cnt[idx] = 0;          // restore invariant for next replay
            running += v[i];
        }
    }
}

// ---------------- [side 4] deterministic scatter via per-edge rank (unroll x2) ----------------
__global__ void scatter_kernel(const int* __restrict__ ei, int E, int T) {
    int t = blockIdx.x * blockDim.x + threadIdx.x;
    if (t >= T) return;
#pragma unroll
    for (int j = 0; j < 2; j++) {
        int e = t + j * T;
        if (e < E) {
            int src = __ldg(&ei[e]);
            int dst = __ldg(&ei[E + e]);
            int rank = g_rank[e];
            g_csrc[__ldg(&g_row[dst]) + 1 + rank] = src;
        }
    }
}

// ---------------- [main 1] layer 1 GEMM (fp16 HMMA) + fused scores + gmax ----------------
__global__ void __launch_bounds__(256) gemm1_tc_kernel(
    const float* __restrict__ A, const float* __restrict__ W,
    const float* __restrict__ att_s, const float* __restrict__ att_d, int n) {
    __shared__ unsigned sAh[128][20];   // [row][k2] packed half2 (k2=0..15 used)
    __shared__ unsigned sWt[128][21];   // [col][k2] packed half2

    int tid = threadIdx.x;
    int warp = tid >> 5, lane = tid & 31;
    int gid = lane >> 2, tig = lane & 3;
    int mwarp = warp >> 2, nwarp = warp & 3;
    int row0 = blockIdx.x * 128;

    float acc[4][4][4];
#pragma unroll
    for (int mt = 0; mt < 4; mt++)
#pragma unroll
        for (int nt = 0; nt < 4; nt++)
#pragma unroll
            for (int r = 0; r < 4; r++) acc[mt][nt][r] = 0.f;

    for (int kc = 0; kc < 4; kc++) {
        int k0 = kc * 32;
        __syncthreads();
#pragma unroll
        for (int rep = 0; rep < 4; rep++) {
            int f = tid + rep * 256;
            int r = f >> 3, c4 = f & 7;
            int gr = row0 + r;
            float4 v = make_float4(0.f, 0.f, 0.f, 0.f);
            if (gr < n) v = *(const float4*)&A[gr * 128 + k0 + c4 * 4];
            sAh[r][c4 * 2 + 0] = pack_half2(v.x, v.y);
            sAh[r][c4 * 2 + 1] = pack_half2(v.z, v.w);
        }
#pragma unroll
        for (int rep = 0; rep < 8; rep++) {
            int f = tid + rep * 256;
            int c = f & 127, k2 = f >> 7;
            float w0 = __ldg(&W[(k0 + 2 * k2) * 128 + c]);
            float w1 = __ldg(&W[(k0 + 2 * k2 + 1) * 128 + c]);
            sWt[c][k2] = pack_half2(w0, w1);
        }
        __syncthreads();
#pragma unroll
        for (int ks = 0; ks < 2; ks++) {
            int kb = ks * 8;
            unsigned b[4][2], a[4][4];
#pragma unroll
            for (int nt = 0; nt < 4; nt++) {
                int c = nwarp * 32 + nt * 8 + gid;
                b[nt][0] = sWt[c][kb + tig];
                b[nt][1] = sWt[c][kb + tig + 4];
            }
#pragma unroll
            for (int mt = 0; mt < 4; mt++) {
                int r = mwarp * 64 + mt * 16 + gid;
                a[mt][0] = sAh[r][kb + tig];
                a[mt][1] = sAh[r + 8][kb + tig];
                a[mt][2] = sAh[r][kb + tig + 4];
                a[mt][3] = sAh[r + 8][kb + tig + 4];
            }
#pragma unroll
            for (int mt = 0; mt < 4; mt++)
#pragma unroll
                for (int nt = 0; nt < 4; nt++) mma_f16(acc[mt][nt], a[mt], b[nt]);
        }
    }

    float asr[8], adr[8];
#pragma unroll
    for (int nt = 0; nt < 4; nt++) {
        int c = nwarp * 32 + nt * 8 + tig * 2;
        asr[nt * 2 + 0] = att_s[c];
        asr[nt * 2 + 1] = att_s[c + 1];
        adr[nt * 2 + 0] = att_d[c];
        adr[nt * 2 + 1] = att_d[c + 1];
    }
    float mxs = __int_as_float(0xff800000), mxd = __int_as_float(0xff800000);
#pragma unroll
    for (int mt = 0; mt < 4; mt++) {
#pragma unroll
        for (int half = 0; half < 2; half++) {
            int r = row0 + mwarp * 64 + mt * 16 + gid + half * 8;
            float sa = 0.f, sd = 0.f;
            if (r < n) {
#pragma unroll
                for (int nt = 0; nt < 4; nt++) {
                    float c0 = acc[mt][nt][half * 2 + 0];
                    float c1 = acc[mt][nt][half * 2 + 1];
                    int col = nwarp * 32 + nt * 8 + tig * 2;
                    *(__half2*)&g_h1h[r * 128 + col] =
                        __float22half2_rn(make_float2(c0, c1));
                    sa += c0 * asr[nt * 2] + c1 * asr[nt * 2 + 1];
                    sd += c0 * adr[nt * 2] + c1 * adr[nt * 2 + 1];
                }
            }
            sa += __shfl_xor_sync(0xffffffffu, sa, 1);
            sa += __shfl_xor_sync(0xffffffffu, sa, 2);
            sd += __shfl_xor_sync(0xffffffffu, sd, 1);
            sd += __shfl_xor_sync(0xffffffffu, sd, 2);
            if (r < n) {
                mxs = fmaxf(mxs, sa);
                mxd = fmaxf(mxd, sd);
                if (tig == 0) {
                    g_as1[r * 4 + nwarp] = sa;
                    g_ad1[r * 4 + nwarp] = sd;
                }
            }
        }
    }
#pragma unroll
    for (int off = 16; off > 0; off >>= 1) {
        mxs = fmaxf(mxs, __shfl_xor_sync(0xffffffffu, mxs, off));
        mxd = fmaxf(mxd, __shfl_xor_sync(0xffffffffu, mxd, off));
    }
    if (lane == 0) {
        atomicMaxF(&g_gmax[nwarp], mxs);
        atomicMaxF(&g_gmax[4 + nwarp], mxd);
    }
}

// ---------------- [main 2] layer 1 gather (warp/dst), fp16 out; 64-thread blocks ----------------
__global__ void __launch_bounds__(64) gat1_gather_kernel(
    const float* __restrict__ b1,
    const float* __restrict__ gamma,
    const float* __restrict__ beta,
    const float* __restrict__ mean,
    const float* __restrict__ var, int n) {
    int w = (blockIdx.x * blockDim.x + threadIdx.x) >> 5;
    int lane = threadIdx.x & 31;
    if (w >= n) return;
    int h = lane >> 3;
    int beg = g_row[w], end = g_row[w + 1];
    float ad = g_ad1[w * 4 + h];
    float ub = lrelu(g_gmax[h] + g_gmax[4 + h]);

    float4 acc = make_float4(0.f, 0.f, 0.f, 0.f);
    float ssum = 0.f;
    int cb = lane * 4;
    int e = beg;
    for (; e + 8 <= end; e += 8) {
        int sv[8];
#pragma unroll
        for (int j = 0; j < 8; j++) sv[j] = __ldg(&g_csrc[e + j]);
        float av[8];
#pragma unroll
        for (int j = 0; j < 8; j++) av[j] = __ldg(&g_as1[sv[j] * 4 + h]);
        uint2 hv[8];
#pragma unroll
        for (int j = 0; j < 8; j++) hv[j] = __ldg((const uint2*)&g_h1h[sv[j] * 128 + cb]);
#pragma unroll
        for (int j = 0; j < 8; j++) {
            float p = __expf(lrelu(av[j] + ad) - ub);
            ssum += p;
            float2 f01 = __half22float2(*(__half2*)&hv[j].x);
            float2 f23 = __half22float2(*(__half2*)&hv[j].y);
            acc.x += p * f01.x;
            acc.y += p * f01.y;
            acc.z += p * f23.x;
            acc.w += p * f23.y;
        }
    }
    for (; e + 4 <= end; e += 4) {
        int sv[4];
#pragma unroll
        for (int j = 0; j < 4; j++) sv[j] = __ldg(&g_csrc[e + j]);
        float av[4];
#pragma unroll
        for (int j = 0; j < 4; j++) av[j] = __ldg(&g_as1[sv[j] * 4 + h]);
        uint2 hv[4];
#pragma unroll
        for (int j = 0; j < 4; j++) hv[j] = __ldg((const uint2*)&g_h1h[sv[j] * 128 + cb]);
#pragma unroll
        for (int j = 0; j < 4; j++) {
            float p = __expf(lrelu(av[j] + ad) - ub);
            ssum += p;
            float2 f01 = __half22float2(*(__half2*)&hv[j].x);
            float2 f23 = __half22float2(*(__half2*)&hv[j].y);
            acc.x += p * f01.x;
            acc.y += p * f01.y;
            acc.z += p * f23.x;
            acc.w += p * f23.y;
        }
    }
    for (; e < end; e++) {
        int s0 = __ldg(&g_csrc[e]);
        float a0 = __ldg(&g_as1[s0 * 4 + h]);
        uint2 v0 = __ldg((const uint2*)&g_h1h[s0 * 128 + cb]);
        float p0 = __expf(lrelu(a0 + ad) - ub);
        ssum += p0;
        float2 f01 = __half22float2(*(__half2*)&v0.x);
        float2 f23 = __half22float2(*(__half2*)&v0.y);
        acc.x += p0 * f01.x;
        acc.y += p0 * f01.y;
        acc.z += p0 * f23.x;
        acc.w += p0 * f23.y;
    }

    float inv = 1.f / ssum;
    float o[4];
#pragma unroll
    for (int j = 0; j < 4; j++) {
        float v = ((&acc.x)[j]) * inv + b1[cb + j];
        v = gamma[cb + j] * (v - mean[cb + j]) * rsqrtf(var[cb + j] + EPS_BN) + beta[cb + j];
        o[j] = fmaxf(v, 0.f);
    }
    __half2 p0 = __float22half2_rn(make_float2(o[0], o[1]));
    __half2 p1 = __float22half2_rn(make_float2(o[2], o[3]));
    uint2 pk;
    pk.x = *(unsigned*)&p0;
    pk.y = *(unsigned*)&p1;
    *(uint2*)&g_acch[w * 128 + cb] = pk;
}

// ---------------- [main 3] layer 2 GEMM (fp16 HMMA, fp16 A in): h2 -> fp16, scores, gmax ----------------
__global__ void __launch_bounds__(256) gemm2_tc_kernel(
    const float* __restrict__ W,
    const float* __restrict__ att_s, const float* __restrict__ att_d, int n) {
    __shared__ unsigned sAh[128][20];
    __shared__ unsigned sWt[64][21];

    int tid = threadIdx.x;
    int warp = tid >> 5, lane = tid & 31;
    int gid = lane >> 2, tig = lane & 3;
    int row0 = blockIdx.x * 128;

    float acc[8][4];
#pragma unroll
    for (int nt = 0; nt < 8; nt++)
#pragma unroll
        for (int r = 0; r < 4; r++) acc[nt][r] = 0.f;

    for (int kc = 0; kc < 4; kc++) {
        int k0 = kc * 32;
        __syncthreads();
#pragma unroll
        for (int rep = 0; rep < 4; rep++) {
            int f = tid + rep * 256;
            int r = f >> 3, c4 = f & 7;
            int gr = row0 + r;
            uint2 hv = make_uint2(0u, 0u);
            if (gr < n) hv = *(const uint2*)&g_acch[gr * 128 + k0 + c4 * 4];
            sAh[r][c4 * 2 + 0] = hv.x;
            sAh[r][c4 * 2 + 1] = hv.y;
        }
#pragma unroll
        for (int rep = 0; rep < 4; rep++) {
            int f = tid + rep * 256;
            int c = f & 63, k2 = f >> 6;
            float w0 = __ldg(&W[(k0 + 2 * k2) * 64 + c]);
            float w1 = __ldg(&W[(k0 + 2 * k2 + 1) * 64 + c]);
            sWt[c][k2] = pack_half2(w0, w1);
        }
        __syncthreads();
#pragma unroll
        for (int ks = 0; ks < 2; ks++) {
            int kb = ks * 8;
            unsigned a[4], b[8][2];
            {
                int r = warp * 16 + gid;
                a[0] = sAh[r][kb + tig];
                a[1] = sAh[r + 8][kb + tig];
                a[2] = sAh[r][kb + tig + 4];
                a[3] = sAh[r + 8][kb + tig + 4];
            }
#pragma unroll
            for (int nt = 0; nt < 8; nt++) {
                int c = nt * 8 + gid;
                b[nt][0] = sWt[c][kb + tig];
                b[nt][1] = sWt[c][kb + tig + 4];
            }
#pragma unroll
            for (int nt = 0; nt < 8; nt++) mma_f16(acc[nt], a, b[nt]);
        }
    }

    float asr[16], adr[16];
#pragma unroll
    for (int nt = 0; nt < 8; nt++) {
        int c = nt * 8 + tig * 2;
        asr[nt * 2 + 0] = att_s[c];
        asr[nt * 2 + 1] = att_s[c + 1];
        adr[nt * 2 + 0] = att_d[c];
        adr[nt * 2 + 1] = att_d[c + 1];
    }
    float mxs = __int_as_float(0xff800000), mxd = __int_as_float(0xff800000);
#pragma unroll
    for (int half = 0; half < 2; half++) {
        int r = row0 + warp * 16 + gid + half * 8;
        float sa = 0.f, sd = 0.f;
        if (r < n) {
#pragma unroll
            for (int nt = 0; nt < 8; nt++) {
                float c0 = acc[nt][half * 2 + 0];
                float c1 = acc[nt][half * 2 + 1];
                int col = nt * 8 + tig * 2;
                *(__half2*)&g_h1h[r * 64 + col] =
                    __float22half2_rn(make_float2(c0, c1));
                sa += c0 * asr[nt * 2] + c1 * asr[nt * 2 + 1];
                sd += c0 * adr[nt * 2] + c1 * adr[nt * 2 + 1];
            }
        }
        sa += __shfl_xor_sync(0xffffffffu, sa, 1);
        sa += __shfl_xor_sync(0xffffffffu, sa, 2);
        sd += __shfl_xor_sync(0xffffffffu, sd, 1);
        sd += __shfl_xor_sync(0xffffffffu, sd, 2);
        if (r < n) {
            mxs = fmaxf(mxs, sa);
            mxd = fmaxf(mxd, sd);
            if (tig == 0) {
                g_as2[r] = sa;
                g_ad2[r] = sd;
            }
        }
    }
#pragma unroll
    for (int off = 16; off > 0; off >>= 1) {
        mxs = fmaxf(mxs, __shfl_xor_sync(0xffffffffu, mxs, off));
        mxd = fmaxf(mxd, __shfl_xor_sync(0xffffffffu, mxd, off));
    }
    if (lane == 0) {
        atomicMaxF(&g_gmax2[0], mxs);
        atomicMaxF(&g_gmax2[1], mxd);
    }
}

// ---------------- [main 4] layer 2 gather (warp/dst), fp16 h; 64-thread blocks ----------------
__global__ void __launch_bounds__(64) gat2_gather_kernel(
    float* __restrict__ out,
    const float* __restrict__ b2,
    const float* __restrict__ gamma,
    const float* __restrict__ beta,
    const float* __restrict__ mean,
    const float* __restrict__ var, int n) {
    int w = (blockIdx.x * blockDim.x + threadIdx.x) >> 5;
    int lane = threadIdx.x & 31;
    if (w >= n) return;
    int beg = g_row[w], end = g_row[w + 1];
    float ad = g_ad2[w];
    float ub = lrelu(g_gmax2[0] + g_gmax2[1]);

    float2 acc = make_float2(0.f, 0.f);
    float ssum = 0.f;
    int cb = lane * 2;
    int e = beg;
    for (; e + 8 <= end; e += 8) {
        int sv[8];
#pragma unroll
        for (int j = 0; j < 8; j++) sv[j] = __ldg(&g_csrc[e + j]);
        float av[8];
#pragma unroll
        for (int j = 0; j < 8; j++) av[j] = __ldg(&g_as2[sv[j]]);
        unsigned hv[8];
#pragma unroll
        for (int j = 0; j < 8; j++) hv[j] = __ldg((const unsigned*)&g_h1h[sv[j] * 64 + cb]);
#pragma unroll
        for (int j = 0; j < 8; j++) {
            float p = __expf(lrelu(av[j] + ad) - ub);
            ssum += p;
            float2 f = __half22float2(*(__half2*)&hv[j]);
            acc.x += p * f.x;
            acc.y += p * f.y;
        }
    }
    for (; e + 4 <= end; e += 4) {
        int sv[4];
#pragma unroll
        for (int j = 0; j < 4; j++) sv[j] = __ldg(&g_csrc[e + j]);
        float av[4];
#pragma unroll
        for (int j = 0; j < 4; j++) av[j] = __ldg(&g_as2[sv[j]]);
        unsigned hv[4];
#pragma unroll
        for (int j = 0; j < 4; j++) hv[j] = __ldg((const unsigned*)&g_h1h[sv[j] * 64 + cb]);
#pragma unroll
        for (int j = 0; j < 4; j++) {
            float p = __expf(lrelu(av[j] + ad) - ub);
            ssum += p;
            float2 f = __half22float2(*(__half2*)&hv[j]);
            acc.x += p * f.x;
            acc.y += p * f.y;
        }
    }
    for (; e < end; e++) {
        int s0 = __ldg(&g_csrc[e]);
        float a0 = __ldg(&g_as2[s0]);
        unsigned v0 = __ldg((const unsigned*)&g_h1h[s0 * 64 + cb]);
        float p0 = __expf(lrelu(a0 + ad) - ub);
        ssum += p0;
        float2 f = __half22float2(*(__half2*)&v0);
        acc.x += p0 * f.x;
        acc.y += p0 * f.y;
    }

    float inv = 1.f / ssum;
    float vx = acc.x * inv + b2[cb];
    float vy = acc.y * inv + b2[cb + 1];
    vx = gamma[cb] * (vx - mean[cb]) * rsqrtf(var[cb] + EPS_BN) + beta[cb];
    vy = gamma[cb + 1] * (vy - mean[cb + 1]) * rsqrtf(var[cb + 1] + EPS_BN) + beta[cb + 1];
    *(float2*)&out[w * 64 + cb] = make_float2(vx, vy);
}

// ---------------- launcher: fork CSR || gemm1; sequential post-join chain ----------------
extern "C" void kernel_launch(void* const* d_in, const int* in_sizes, int n_in,
                              void* d_out, int out_size) {
    const float* x        = (const float*)d_in[0];
    const int*   ei       = (const int*)d_in[1];   // int32 (JAX demotes int64)
    const float* W1       = (const float*)d_in[2];
    const float* att_src1 = (const float*)d_in[3];
    const float* att_dst1 = (const float*)d_in[4];
    const float* b1       = (const float*)d_in[5];
    const float* bn1_g    = (const float*)d_in[6];
    const float* bn1_b    = (const float*)d_in[7];
    const float* bn1_m    = (const float*)d_in[8];
    const float* bn1_v    = (const float*)d_in[9];
    const float* W2       = (const float*)d_in[10];
    const float* att_src2 = (const float*)d_in[11];
    const float* att_dst2 = (const float*)d_in[12];
    const float* b2       = (const float*)d_in[13];
    const float* bn2_g    = (const float*)d_in[14];
    const float* bn2_b    = (const float*)d_in[15];
    const float* bn2_m    = (const float*)d_in[16];
    const float* bn2_v    = (const float*)d_in[17];
    float* out = (float*)d_out;

    int n = in_sizes[0] / 128;
    int E = in_sizes[1] / 2;
    int nb = (n + SCAN_CHUNK - 1) / SCAN_CHUNK;

    const int B = 256;

    static cudaStream_t side = nullptr;
    static cudaEvent_t evFork = nullptr, evJoin = nullptr;
    if (side == nullptr) {
        cudaStreamCreateWithFlags(&side, cudaStreamNonBlocking);
        cudaEventCreateWithFlags(&evFork, cudaEventDisableTiming);
        cudaEventCreateWithFlags(&evJoin, cudaEventDisableTiming);
    }

    // ---- fork: CSR build on side stream, gemm1 on main stream ----
    cudaEventRecord(evFork, 0);
    cudaStreamWaitEvent(side, evFork, 0);

    int Th = (E + 3) / 4;   // hist unroll x4
    int Ts = (E + 1) / 2;   // scatter unroll x2
    hist_kernel<<<(Th + B - 1) / B, B, 0, side>>>(ei, E, Th);
    scan_part_kernel<<<nb, 256, 0, side>>>(n);
    scan_down_kernel<<<nb, 256, 0, side>>>(n, nb);
    scatter_kernel<<<(Ts + B - 1) / B, B, 0, side>>>(ei, E, Ts);
    cudaEventRecord(evJoin, side);

    gemm1_tc_kernel<<<(n + 127) / 128, 256>>>(x, W1, att_src1, att_dst1, n);

    // ---- join CSR, then the sequential chain (gathers in 64-thread blocks) ----
    cudaStreamWaitEvent(0, evJoin, 0);
    gat1_gather_kernel<<<(n * 32 + 63) / 64, 64>>>(b1, bn1_g, bn1_b, bn1_m, bn1_v, n);
    gemm2_tc_kernel<<<(n + 127) / 128, 256>>>(W2, att_src2, att_dst2, n);
    gat2_gather_kernel<<<(n * 32 + 63) / 64, 64>>>(out, b2, bn2_g, bn2_b, bn2_m, bn2_v, n);
}